// round 7
// baseline (speedup 1.0000x reference)
#include <cuda_runtime.h>
#include <math.h>
#include <stdint.h>

#define HIDDEN 2560
#define NH 32
#define NKV 8
#define HD 80
#define BATCH 2
#define SEQ 2048
#define M_TOK (BATCH * SEQ)   // 4096

// ---------------- scratch (static device globals; no runtime alloc) ----------
__device__ float g_q[M_TOK * NH * HD];
__device__ float g_k[M_TOK * NKV * HD];
__device__ float g_v[M_TOK * NKV * HD];
__device__ float g_o[M_TOK * NH * HD];        // attn out: tf32-rounded, K-permuted
__device__ float g_xc[M_TOK * HIDDEN];        // x: tf32-rounded, K-permuted
__device__ float g_wqc[HIDDEN * NH * HD];     // weights: interleaved B' layout
__device__ float g_wkc[HIDDEN * NKV * HD];
__device__ float g_wvc[HIDDEN * NKV * HD];
__device__ float g_woc[NH * HD * HIDDEN];

__device__ __forceinline__ unsigned f2tf32(float x) {
    unsigned y;
    asm("cvt.rna.tf32.f32 %0, %1;" : "=r"(y) : "f"(x));
    return y;
}
__device__ __forceinline__ float rtf(float x) {
    return __uint_as_float(f2tf32(x));
}

__device__ __forceinline__ void mma_tf32(float* c, const unsigned* a,
                                         unsigned b0, unsigned b1) {
    asm volatile(
        "mma.sync.aligned.m16n8k8.row.col.f32.tf32.tf32.f32 "
        "{%0,%1,%2,%3}, {%4,%5,%6,%7}, {%8,%9}, {%0,%1,%2,%3};"
        : "+f"(c[0]), "+f"(c[1]), "+f"(c[2]), "+f"(c[3])
        : "r"(a[0]), "r"(a[1]), "r"(a[2]), "r"(a[3]),
          "r"(b0), "r"(b1));
}

__device__ __forceinline__ void cp_async16(void* smem_ptr, const void* gptr) {
    unsigned saddr = (unsigned)__cvta_generic_to_shared(smem_ptr);
    asm volatile("cp.async.cg.shared.global [%0], [%1], 16;\n"
                 :: "r"(saddr), "l"(gptr));
}
__device__ __forceinline__ void cp_commit() {
    asm volatile("cp.async.commit_group;\n");
}
__device__ __forceinline__ void cp_wait0() {
    asm volatile("cp.async.wait_group 0;\n");
}

// ---------------- prep A: tf32 round + permute K within groups of 8 ----------
// pos(k&7): [k0,k4,k1,k5,k2,k6,k3,k7]
__global__ void prep_A_kernel(const float* __restrict__ in,
                              float* __restrict__ out, int ngroups)
{
    int g = blockIdx.x * blockDim.x + threadIdx.x;
    if (g >= ngroups) return;
    const float4* ip = (const float4*)in + (size_t)g * 2;
    float4 a = ip[0], b = ip[1];
    float4 o0 = make_float4(rtf(a.x), rtf(b.x), rtf(a.y), rtf(b.y));
    float4 o1 = make_float4(rtf(a.z), rtf(b.z), rtf(a.w), rtf(b.w));
    float4* op = (float4*)out + (size_t)g * 2;
    op[0] = o0; op[1] = o1;
}

// ---------------- prep B: [K,N] -> interleaved [K/8][4(lr)][N][2(h)] + round --
__global__ void prep_B_kernel(const float* __restrict__ in,
                              float* __restrict__ out,
                              int Kdim, int Ndim, int total)
{
    int id = blockIdx.x * blockDim.x + threadIdx.x;
    if (id >= total) return;
    int nh  = Ndim >> 1;
    int n2  = id % nh;
    int rest = id / nh;
    int lr  = rest & 3;
    int g   = rest >> 2;
    int klo = g * 8 + lr;
    const float* plo = in + (size_t)klo * Ndim + n2 * 2;
    const float* phi = plo + 4 * (size_t)Ndim;
    float4 o = make_float4(rtf(plo[0]), rtf(phi[0]), rtf(plo[1]), rtf(phi[1]));
    ((float4*)out)[(size_t)(g * 4 + lr) * nh + n2] = o;
}

// ---------------- pipelined TF32 GEMM (vectorized frags), 3 segments ----------
// A': [M,K] tf32-rounded, K-permuted. B': interleaved layout above.
// Block tile 128x128, BK=32, 256 threads (8 warps 4x2), warp tile 32x64.
#define ASTR 40
#define BLRS 264                        // B lr stride (2*128 + 8)
#define BKGS (4 * BLRS)                 // B kgroup stride = 1056
#define ASZ  (128 * ASTR)               // 5120 floats
#define BSZ  (4 * BKGS)                 // 4224 floats
#define STG  (ASZ + BSZ)                // 9344 floats
#define GEMM_SMEM (2 * STG * 4)         // 74752 bytes

__global__ __launch_bounds__(256) void tf32_gemm3_kernel(
    const float* __restrict__ A,
    const float* __restrict__ B0, float* __restrict__ C0, int N0, int xs0,
    const float* __restrict__ B1, float* __restrict__ C1, int N1, int xs1,
    const float* __restrict__ B2, float* __restrict__ C2, int N2,
    int M, int K)
{
    extern __shared__ float smp[];

    const int bx = blockIdx.x;
    const float* B; float* C; int N; int bxl;
    if (bx < xs0)      { B = B0; C = C0; N = N0; bxl = bx; }
    else if (bx < xs1) { B = B1; C = C1; N = N1; bxl = bx - xs0; }
    else               { B = B2; C = C2; N = N2; bxl = bx - xs1; }

    const int tid  = threadIdx.x;
    const int lane = tid & 31;
    const int warp = tid >> 5;
    const int wm   = (warp & 3) * 32;
    const int wn   = (warp >> 2) * 64;
    const int bm   = blockIdx.y * 128;
    const int bn   = bxl * 128;
    const int lq   = lane >> 2;
    const int lr   = lane & 3;

    // A copy coords: 1024 chunks, 4/thread
    const int arow = tid >> 3;            // 0..31 (+32*i)
    const int ac4  = (tid & 7) * 4;       // 0..28
    // B copy coords: idx = tid + i*256 -> kg, blr, n2
    float acc[2][8][4];
    #pragma unroll
    for (int i = 0; i < 2; i++)
        #pragma unroll
        for (int j = 0; j < 8; j++)
            #pragma unroll
            for (int r = 0; r < 4; r++) acc[i][j][r] = 0.f;

    const int T = K / 32;

    // prefetch tile 0 -> stage 0
    {
        float* sA = smp;
        float* sB = smp + ASZ;
        #pragma unroll
        for (int i = 0; i < 4; i++) {
            int row = arow + i * 32;
            cp_async16(&sA[row * ASTR + ac4], A + (size_t)(bm + row) * K + ac4);
        }
        #pragma unroll
        for (int i = 0; i < 4; i++) {
            int idx = tid + i * 256;
            int kg  = idx >> 8;
            int blr = (idx >> 6) & 3;
            int n2  = idx & 63;
            cp_async16(&sB[kg * BKGS + blr * BLRS + n2 * 4],
                       B + ((size_t)(kg * 4 + blr)) * (N * 2)
                         + (size_t)(bn + 2 * n2) * 2);
        }
        cp_commit();
    }

    for (int t = 0; t < T; t++) {
        cp_wait0();
        __syncthreads();

        if (t + 1 < T) {
            float* sA = smp + ((t + 1) & 1) * STG;
            float* sB = sA + ASZ;
            int k0 = (t + 1) * 32;
            #pragma unroll
            for (int i = 0; i < 4; i++) {
                int row = arow + i * 32;
                cp_async16(&sA[row * ASTR + ac4],
                           A + (size_t)(bm + row) * K + k0 + ac4);
            }
            #pragma unroll
            for (int i = 0; i < 4; i++) {
                int idx = tid + i * 256;
                int kg  = idx >> 8;
                int blr = (idx >> 6) & 3;
                int n2  = idx & 63;
                cp_async16(&sB[kg * BKGS + blr * BLRS + n2 * 4],
                           B + ((size_t)(((t + 1) * 4 + kg) * 4 + blr)) * (N * 2)
                             + (size_t)(bn + 2 * n2) * 2);
            }
        }
        cp_commit();

        const float* sA = smp + (t & 1) * STG;
        const float* sB = sA + ASZ;
        #pragma unroll
        for (int ks = 0; ks < 4; ks++) {
            unsigned af[2][4];
            #pragma unroll
            for (int mi = 0; mi < 2; mi++) {
                int m = wm + mi * 16 + lq;
                float2 fa = *(const float2*)(sA + m * ASTR + ks * 8 + 2 * lr);
                float2 fb = *(const float2*)(sA + (m + 8) * ASTR + ks * 8 + 2 * lr);
                af[mi][0] = __float_as_uint(fa.x);
                af[mi][1] = __float_as_uint(fb.x);
                af[mi][2] = __float_as_uint(fa.y);
                af[mi][3] = __float_as_uint(fb.y);
            }
            unsigned bf[8][2];
            #pragma unroll
            for (int ni = 0; ni < 8; ni++) {
                int n = wn + ni * 8 + lq;
                float2 fb = *(const float2*)(sB + ks * BKGS + lr * BLRS + n * 2);
                bf[ni][0] = __float_as_uint(fb.x);
                bf[ni][1] = __float_as_uint(fb.y);
            }
            #pragma unroll
            for (int mi = 0; mi < 2; mi++)
                #pragma unroll
                for (int ni = 0; ni < 8; ni++)
                    mma_tf32(acc[mi][ni], af[mi], bf[ni][0], bf[ni][1]);
        }
        __syncthreads();
    }

    #pragma unroll
    for (int mi = 0; mi < 2; mi++) {
        int m = bm + wm + mi * 16 + lq;
        #pragma unroll
        for (int ni = 0; ni < 8; ni++) {
            int n = bn + wn + ni * 8 + lr * 2;
            float2* p0 = (float2*)(C + (size_t)m * N + n);
            float2* p1 = (float2*)(C + (size_t)(m + 8) * N + n);
            *p0 = make_float2(acc[mi][ni][0], acc[mi][ni][1]);
            *p1 = make_float2(acc[mi][ni][2], acc[mi][ni][3]);
        }
    }
}

// ---------------- fused RoPE over q and k --------------------------------------
__global__ void rope_fused_kernel(float* __restrict__ qb, float* __restrict__ kb,
                                  const float* __restrict__ cosf,
                                  const float* __restrict__ sinf,
                                  int tq, int total)
{
    int idx = blockIdx.x * blockDim.x + threadIdx.x;
    if (idx >= total) return;
    float* t; int nheads; int li;
    if (idx < tq) { t = qb; nheads = NH;  li = idx; }
    else          { t = kb; nheads = NKV; li = idx - tq; }

    int i   = li % (HD / 2);
    int h   = (li / (HD / 2)) % nheads;
    int tok = li / ((HD / 2) * nheads);
    int s   = tok % SEQ;

    float* p = t + (size_t)tok * nheads * HD + h * HD;
    float x1 = p[i];
    float x2 = p[i + HD / 2];
    float c1 = cosf[s * HD + i];
    float s1 = sinf[s * HD + i];
    float c2 = cosf[s * HD + i + HD / 2];
    float s2 = sinf[s * HD + i + HD / 2];
    p[i]          = x1 * c1 - x2 * s1;
    p[i + HD / 2] = x2 * c2 + x1 * s2;
}

// ---------------- TF32 tensor-core flash attention -----------------------------
// Epilogue writes tf32-rounded, K-permuted output for the Wo GEMM.
#define QSTR 84
#define PSTR 132

__global__ __launch_bounds__(256) void attn_tc_kernel(
    const float* __restrict__ q, const float* __restrict__ k,
    const float* __restrict__ v, float* __restrict__ o)
{
    extern __shared__ unsigned sm[];
    unsigned* Qs = sm;
    unsigned* Ks = Qs + 128 * QSTR;
    unsigned* Vt = Ks + 128 * QSTR;
    unsigned* Ps = Vt + 80 * PSTR;

    const int b    = blockIdx.z;
    const int h    = blockIdx.y;
    const int qt   = blockIdx.x;
    const int kvh  = h >> 2;
    const int tid  = threadIdx.x;
    const int lane = tid & 31;
    const int warp = tid >> 5;
    const int lq   = lane >> 2;
    const int lr   = lane & 3;
    const int wr   = warp * 16;
    const float scale = rsqrtf((float)HD);

    #pragma unroll
    for (int i = 0; i < 10; i++) {
        int f   = tid + i * 256;
        int row = f / 20;
        int c4  = (f % 20) * 4;
        float4 a = *(const float4*)(q + ((size_t)(b * SEQ + qt * 128 + row)) * (NH * HD)
                                      + h * HD + c4);
        Qs[row * QSTR + c4 + 0] = f2tf32(a.x);
        Qs[row * QSTR + c4 + 1] = f2tf32(a.y);
        Qs[row * QSTR + c4 + 2] = f2tf32(a.z);
        Qs[row * QSTR + c4 + 3] = f2tf32(a.w);
    }

    float oacc[10][4];
    #pragma unroll
    for (int i = 0; i < 10; i++)
        #pragma unroll
        for (int j = 0; j < 4; j++) oacc[i][j] = 0.f;
    float m0 = -INFINITY, m1 = -INFINITY;
    float l0 = 0.f, l1 = 0.f;

    const int row0 = qt * 128 + wr + lq;
    const int row1 = row0 + 8;

    for (int kt = 0; kt <= qt; kt++) {
        __syncthreads();
        #pragma unroll
        for (int i = 0; i < 10; i++) {
            int f   = tid + i * 256;
            int row = f / 20;
            int c4  = (f % 20) * 4;
            size_t g = ((size_t)(b * SEQ + kt * 128 + row)) * (NKV * HD) + kvh * HD + c4;
            float4 kk = *(const float4*)(k + g);
            Ks[row * QSTR + c4 + 0] = f2tf32(kk.x);
            Ks[row * QSTR + c4 + 1] = f2tf32(kk.y);
            Ks[row * QSTR + c4 + 2] = f2tf32(kk.z);
            Ks[row * QSTR + c4 + 3] = f2tf32(kk.w);
            float4 vv = *(const float4*)(v + g);
            Vt[(c4 + 0) * PSTR + row] = f2tf32(vv.x);
            Vt[(c4 + 1) * PSTR + row] = f2tf32(vv.y);
            Vt[(c4 + 2) * PSTR + row] = f2tf32(vv.z);
            Vt[(c4 + 3) * PSTR + row] = f2tf32(vv.w);
        }
        __syncthreads();

        float sc[16][4];
        #pragma unroll
        for (int ni = 0; ni < 16; ni++)
            #pragma unroll
            for (int j = 0; j < 4; j++) sc[ni][j] = 0.f;

        #pragma unroll
        for (int ks = 0; ks < 10; ks++) {
            unsigned af[4];
            af[0] = Qs[(wr + lq    ) * QSTR + ks * 8 + lr    ];
            af[1] = Qs[(wr + lq + 8) * QSTR + ks * 8 + lr    ];
            af[2] = Qs[(wr + lq    ) * QSTR + ks * 8 + 4 + lr];
            af[3] = Qs[(wr + lq + 8) * QSTR + ks * 8 + 4 + lr];
            #pragma unroll
            for (int ni = 0; ni < 16; ni++) {
                unsigned b0 = Ks[(ni * 8 + lq) * QSTR + ks * 8 + lr    ];
                unsigned b1 = Ks[(ni * 8 + lq) * QSTR + ks * 8 + 4 + lr];
                mma_tf32(sc[ni], af, b0, b1);
            }
        }

        const bool diag = (kt == qt);
        #pragma unroll
        for (int ni = 0; ni < 16; ni++) {
            int c = kt * 128 + ni * 8 + lr * 2;
            sc[ni][0] = (diag && c     > row0) ? -1e30f : sc[ni][0] * scale;
            sc[ni][1] = (diag && c + 1 > row0) ? -1e30f : sc[ni][1] * scale;
            sc[ni][2] = (diag && c     > row1) ? -1e30f : sc[ni][2] * scale;
            sc[ni][3] = (diag && c + 1 > row1) ? -1e30f : sc[ni][3] * scale;
        }

        float rm0 = -1e30f, rm1 = -1e30f;
        #pragma unroll
        for (int ni = 0; ni < 16; ni++) {
            rm0 = fmaxf(rm0, fmaxf(sc[ni][0], sc[ni][1]));
            rm1 = fmaxf(rm1, fmaxf(sc[ni][2], sc[ni][3]));
        }
        rm0 = fmaxf(rm0, __shfl_xor_sync(0xffffffffu, rm0, 1));
        rm0 = fmaxf(rm0, __shfl_xor_sync(0xffffffffu, rm0, 2));
        rm1 = fmaxf(rm1, __shfl_xor_sync(0xffffffffu, rm1, 1));
        rm1 = fmaxf(rm1, __shfl_xor_sync(0xffffffffu, rm1, 2));

        float m0n = fmaxf(m0, rm0);
        float m1n = fmaxf(m1, rm1);
        float a0  = __expf(m0 - m0n);
        float a1  = __expf(m1 - m1n);
        m0 = m0n; m1 = m1n;

        float rs0 = 0.f, rs1 = 0.f;
        #pragma unroll
        for (int ni = 0; ni < 16; ni++) {
            float p0 = __expf(sc[ni][0] - m0n);
            float p1 = __expf(sc[ni][1] - m0n);
            float p2 = __expf(sc[ni][2] - m1n);
            float p3 = __expf(sc[ni][3] - m1n);
            rs0 += p0 + p1;
            rs1 += p2 + p3;
            unsigned* pr0 = &Ps[(wr + lq    ) * PSTR + ni * 8 + lr * 2];
            unsigned* pr1 = &Ps[(wr + lq + 8) * PSTR + ni * 8 + lr * 2];
            pr0[0] = f2tf32(p0); pr0[1] = f2tf32(p1);
            pr1[0] = f2tf32(p2); pr1[1] = f2tf32(p3);
        }
        rs0 += __shfl_xor_sync(0xffffffffu, rs0, 1);
        rs0 += __shfl_xor_sync(0xffffffffu, rs0, 2);
        rs1 += __shfl_xor_sync(0xffffffffu, rs1, 1);
        rs1 += __shfl_xor_sync(0xffffffffu, rs1, 2);
        l0 = l0 * a0 + rs0;
        l1 = l1 * a1 + rs1;

        #pragma unroll
        for (int ni = 0; ni < 10; ni++) {
            oacc[ni][0] *= a0; oacc[ni][1] *= a0;
            oacc[ni][2] *= a1; oacc[ni][3] *= a1;
        }

        __syncwarp();

        #pragma unroll
        for (int ks = 0; ks < 16; ks++) {
            unsigned af[4];
            af[0] = Ps[(wr + lq    ) * PSTR + ks * 8 + lr    ];
            af[1] = Ps[(wr + lq + 8) * PSTR + ks * 8 + lr    ];
            af[2] = Ps[(wr + lq    ) * PSTR + ks * 8 + 4 + lr];
            af[3] = Ps[(wr + lq + 8) * PSTR + ks * 8 + 4 + lr];
            #pragma unroll
            for (int ni = 0; ni < 10; ni++) {
                unsigned b0 = Vt[(ni * 8 + lq) * PSTR + ks * 8 + lr    ];
                unsigned b1 = Vt[(ni * 8 + lq) * PSTR + ks * 8 + 4 + lr];
                mma_tf32(oacc[ni], af, b0, b1);
            }
        }
    }

    // epilogue: tf32-rounded + K-permuted (pos(c) = (c&3)*2 + (c>>2) in 8-groups)
    const float inv0 = 1.0f / l0;
    const float inv1 = 1.0f / l1;
    const int c0 = lr * 2;
    const int c1 = lr * 2 + 1;
    const int p0off = ((c0 & 3) * 2) + (c0 >> 2);   // {0,4,1,5}[lr]
    const int p1off = ((c1 & 3) * 2) + (c1 >> 2);   // {2,6,3,7}[lr]
    #pragma unroll
    for (int ni = 0; ni < 10; ni++) {
        int gbase = h * HD + ni * 8;
        float* o0 = o + (size_t)(b * SEQ + row0) * (NH * HD) + gbase;
        float* o1 = o + (size_t)(b * SEQ + row1) * (NH * HD) + gbase;
        o0[p0off] = rtf(oacc[ni][0] * inv0);
        o0[p1off] = rtf(oacc[ni][1] * inv0);
        o1[p0off] = rtf(oacc[ni][2] * inv1);
        o1[p1off] = rtf(oacc[ni][3] * inv1);
    }
}

// ---------------- launch --------------------------------------------------------
extern "C" void kernel_launch(void* const* d_in, const int* in_sizes, int n_in,
                              void* d_out, int out_size)
{
    const float* x    = (const float*)d_in[0];
    const float* cosf = (const float*)d_in[1];
    const float* sinf = (const float*)d_in[2];
    const float* Wq   = (const float*)d_in[3];
    const float* Wk   = (const float*)d_in[4];
    const float* Wv   = (const float*)d_in[5];
    const float* Wo   = (const float*)d_in[6];
    float* out = (float*)d_out;

    float *qb, *kb, *vb, *ob, *xc, *wqc, *wkc, *wvc, *woc;
    cudaGetSymbolAddress((void**)&qb, g_q);
    cudaGetSymbolAddress((void**)&kb, g_k);
    cudaGetSymbolAddress((void**)&vb, g_v);
    cudaGetSymbolAddress((void**)&ob, g_o);
    cudaGetSymbolAddress((void**)&xc, g_xc);
    cudaGetSymbolAddress((void**)&wqc, g_wqc);
    cudaGetSymbolAddress((void**)&wkc, g_wkc);
    cudaGetSymbolAddress((void**)&wvc, g_wvc);
    cudaGetSymbolAddress((void**)&woc, g_woc);

    // prep A operand (x) and B operands (weights)
    {
        int ng = M_TOK * HIDDEN / 8;
        prep_A_kernel<<<(ng + 255) / 256, 256>>>(x, xc, ng);
        int t;
        t = HIDDEN * (NH * HD) / 4;
        prep_B_kernel<<<(t + 255) / 256, 256>>>(Wq, wqc, HIDDEN, NH * HD, t);
        t = HIDDEN * (NKV * HD) / 4;
        prep_B_kernel<<<(t + 255) / 256, 256>>>(Wk, wkc, HIDDEN, NKV * HD, t);
        prep_B_kernel<<<(t + 255) / 256, 256>>>(Wv, wvc, HIDDEN, NKV * HD, t);
        t = (NH * HD) * HIDDEN / 4;
        prep_B_kernel<<<(t + 255) / 256, 256>>>(Wo, woc, NH * HD, HIDDEN, t);
    }

    cudaFuncSetAttribute(tf32_gemm3_kernel,
                         cudaFuncAttributeMaxDynamicSharedMemorySize, GEMM_SMEM);

    // fused Q/K/V projections
    {
        dim3 g(30, M_TOK / 128);
        tf32_gemm3_kernel<<<g, 256, GEMM_SMEM>>>(
            xc,
            wqc, qb, NH * HD, 20,
            wkc, kb, NKV * HD, 25,
            wvc, vb, NKV * HD,
            M_TOK, HIDDEN);
    }

    // fused RoPE
    {
        int tq = M_TOK * NH * (HD / 2);
        int tk = M_TOK * NKV * (HD / 2);
        int tot = tq + tk;
        rope_fused_kernel<<<(tot + 255) / 256, 256>>>(qb, kb, cosf, sinf, tq, tot);
    }

    // attention
    {
        static const int smem_bytes =
            (128 * QSTR + 128 * QSTR + 80 * PSTR + 128 * PSTR) * 4;
        cudaFuncSetAttribute(attn_tc_kernel,
                             cudaFuncAttributeMaxDynamicSharedMemorySize, smem_bytes);
        dim3 ga(SEQ / 128, NH, BATCH);
        attn_tc_kernel<<<ga, 256, smem_bytes>>>(qb, kb, vb, ob);
    }

    // output projection
    {
        dim3 go(HIDDEN / 128, M_TOK / 128);
        tf32_gemm3_kernel<<<go, 256, GEMM_SMEM>>>(
            ob,
            woc, out, HIDDEN, 20,
            woc, out, HIDDEN, 20,
            woc, out, HIDDEN,
            M_TOK, HIDDEN);
    }
}

// round 8
// speedup vs baseline: 1.2642x; 1.2642x over previous
#include <cuda_runtime.h>
#include <cuda_fp16.h>
#include <math.h>
#include <stdint.h>

#define HIDDEN 2560
#define NH 32
#define NKV 8
#define HD 80
#define BATCH 2
#define SEQ 2048
#define M_TOK (BATCH * SEQ)   // 4096

// ---------------- scratch (static device globals; no runtime alloc) ----------
__device__ float  g_q[M_TOK * NH * HD];
__device__ float  g_k[M_TOK * NKV * HD];
__device__ float  g_v[M_TOK * NKV * HD];
__device__ __half g_oh[M_TOK * NH * HD];       // attn out, half, K-major
__device__ __half g_xh[M_TOK * HIDDEN];        // x rounded to half
__device__ __half g_wqh[HIDDEN * NH * HD];     // weights: transposed [N,K] half
__device__ __half g_wkh[HIDDEN * NKV * HD];
__device__ __half g_wvh[HIDDEN * NKV * HD];
__device__ __half g_woh[NH * HD * HIDDEN];

__device__ __forceinline__ unsigned f2tf32(float x) {
    unsigned y;
    asm("cvt.rna.tf32.f32 %0, %1;" : "=r"(y) : "f"(x));
    return y;
}

__device__ __forceinline__ void mma_tf32(float* c, const unsigned* a,
                                         unsigned b0, unsigned b1) {
    asm volatile(
        "mma.sync.aligned.m16n8k8.row.col.f32.tf32.tf32.f32 "
        "{%0,%1,%2,%3}, {%4,%5,%6,%7}, {%8,%9}, {%0,%1,%2,%3};"
        : "+f"(c[0]), "+f"(c[1]), "+f"(c[2]), "+f"(c[3])
        : "r"(a[0]), "r"(a[1]), "r"(a[2]), "r"(a[3]),
          "r"(b0), "r"(b1));
}

__device__ __forceinline__ void mma_f16(float* c, const unsigned* a,
                                        unsigned b0, unsigned b1) {
    asm volatile(
        "mma.sync.aligned.m16n8k16.row.col.f32.f16.f16.f32 "
        "{%0,%1,%2,%3}, {%4,%5,%6,%7}, {%8,%9}, {%0,%1,%2,%3};"
        : "+f"(c[0]), "+f"(c[1]), "+f"(c[2]), "+f"(c[3])
        : "r"(a[0]), "r"(a[1]), "r"(a[2]), "r"(a[3]),
          "r"(b0), "r"(b1));
}

__device__ __forceinline__ void cp_async16(void* smem_ptr, const void* gptr) {
    unsigned saddr = (unsigned)__cvta_generic_to_shared(smem_ptr);
    asm volatile("cp.async.cg.shared.global [%0], [%1], 16;\n"
                 :: "r"(saddr), "l"(gptr));
}
__device__ __forceinline__ void cp_commit() {
    asm volatile("cp.async.commit_group;\n");
}
__device__ __forceinline__ void cp_wait0() {
    asm volatile("cp.async.wait_group 0;\n");
}

// ---------------- prep: fp32 -> fp16, same layout ------------------------------
__global__ void f2h_kernel(const float* __restrict__ in,
                           __half* __restrict__ out, int n8)
{
    int i = blockIdx.x * blockDim.x + threadIdx.x;
    if (i >= n8) return;
    const float4* ip = (const float4*)in + (size_t)i * 2;
    float4 a = ip[0], b = ip[1];
    __half2 h0 = __floats2half2_rn(a.x, a.y);
    __half2 h1 = __floats2half2_rn(a.z, a.w);
    __half2 h2 = __floats2half2_rn(b.x, b.y);
    __half2 h3 = __floats2half2_rn(b.z, b.w);
    uint4 o;
    o.x = *(unsigned*)&h0; o.y = *(unsigned*)&h1;
    o.z = *(unsigned*)&h2; o.w = *(unsigned*)&h3;
    *((uint4*)out + i) = o;
}

// ---------------- prep: transpose [K,N] fp32 -> [N,K] fp16 ---------------------
__global__ void f2h_transpose_kernel(const float* __restrict__ in,
                                     __half* __restrict__ out,
                                     int Kdim, int Ndim)
{
    __shared__ float t[32][33];
    int n0 = blockIdx.x * 32, k0 = blockIdx.y * 32;
    #pragma unroll
    for (int j = 0; j < 4; j++)
        t[threadIdx.y + j * 8][threadIdx.x] =
            in[(size_t)(k0 + threadIdx.y + j * 8) * Ndim + n0 + threadIdx.x];
    __syncthreads();
    #pragma unroll
    for (int j = 0; j < 4; j++)
        out[(size_t)(n0 + threadIdx.y + j * 8) * Kdim + k0 + threadIdx.x] =
            __float2half_rn(t[threadIdx.x][threadIdx.y + j * 8]);
}

// ---------------- pipelined FP16 GEMM, up to 3 output segments -----------------
// C_s[M,N_s](fp32) = A[M,K](f16) @ Bt_s[N_s,K](f16)^T.
// Block tile 128x128, BK=32, 256 threads (8 warps 4x2), warp tile 32x64.
// m16n8k16 mma; 2 k-chunks per iter. A/B smem rows: 32 halves, stride 40 halves.
#define HSTR 40                         // halves per smem row
#define TILEH (128 * HSTR)              // halves per tile (A or B) = 5120
#define STGH  (2 * TILEH)               // halves per stage = 10240
#define GEMM_SMEM (2 * STGH * 2)        // bytes = 40960

__global__ __launch_bounds__(256) void h16_gemm3_kernel(
    const __half* __restrict__ A,
    const __half* __restrict__ B0, float* __restrict__ C0, int N0, int xs0,
    const __half* __restrict__ B1, float* __restrict__ C1, int N1, int xs1,
    const __half* __restrict__ B2, float* __restrict__ C2, int N2,
    int M, int K)
{
    extern __shared__ __half smh[];

    const int bx = blockIdx.x;
    const __half* B; float* C; int N; int bxl;
    if (bx < xs0)      { B = B0; C = C0; N = N0; bxl = bx; }
    else if (bx < xs1) { B = B1; C = C1; N = N1; bxl = bx - xs0; }
    else               { B = B2; C = C2; N = N2; bxl = bx - xs1; }

    const int tid  = threadIdx.x;
    const int lane = tid & 31;
    const int warp = tid >> 5;
    const int wm   = (warp & 3) * 32;
    const int wn   = (warp >> 2) * 64;
    const int bm   = blockIdx.y * 128;
    const int bn   = bxl * 128;
    const int lq   = lane >> 2;
    const int lr   = lane & 3;

    // copy coords: per tile 512 chunks (128 rows x 4 chunks of 16B), 2/thread
    const int cr = tid >> 2;            // 0..63  (+64)
    const int cc = tid & 3;             // 16B chunk in row

    float acc[2][8][4];
    #pragma unroll
    for (int i = 0; i < 2; i++)
        #pragma unroll
        for (int j = 0; j < 8; j++)
            #pragma unroll
            for (int r = 0; r < 4; r++) acc[i][j][r] = 0.f;

    const int T = K / 32;

    // prefetch tile 0 -> stage 0
    {
        __half* sA = smh;
        __half* sB = smh + TILEH;
        #pragma unroll
        for (int i = 0; i < 2; i++) {
            int r = cr + i * 64;
            cp_async16(sA + r * HSTR + cc * 8, A + (size_t)(bm + r) * K + cc * 8);
            cp_async16(sB + r * HSTR + cc * 8, B + (size_t)(bn + r) * K + cc * 8);
        }
        cp_commit();
    }

    for (int t = 0; t < T; t++) {
        cp_wait0();
        __syncthreads();

        if (t + 1 < T) {
            __half* sA = smh + ((t + 1) & 1) * STGH;
            __half* sB = sA + TILEH;
            int k0 = (t + 1) * 32;
            #pragma unroll
            for (int i = 0; i < 2; i++) {
                int r = cr + i * 64;
                cp_async16(sA + r * HSTR + cc * 8,
                           A + (size_t)(bm + r) * K + k0 + cc * 8);
                cp_async16(sB + r * HSTR + cc * 8,
                           B + (size_t)(bn + r) * K + k0 + cc * 8);
            }
        }
        cp_commit();

        const unsigned* sAu = (const unsigned*)(smh + (t & 1) * STGH);
        const unsigned* sBu = sAu + TILEH / 2;
        #pragma unroll
        for (int ks = 0; ks < 2; ks++) {
            const int c8 = ks * 8;          // word offset of 16-half k-chunk
            unsigned af[2][4];
            #pragma unroll
            for (int mi = 0; mi < 2; mi++) {
                int m = wm + mi * 16 + lq;
                af[mi][0] = sAu[(m    ) * 20 + c8 + lr    ];
                af[mi][1] = sAu[(m + 8) * 20 + c8 + lr    ];
                af[mi][2] = sAu[(m    ) * 20 + c8 + 4 + lr];
                af[mi][3] = sAu[(m + 8) * 20 + c8 + 4 + lr];
            }
            unsigned bf[8][2];
            #pragma unroll
            for (int ni = 0; ni < 8; ni++) {
                int n = wn + ni * 8 + lq;
                bf[ni][0] = sBu[n * 20 + c8 + lr    ];
                bf[ni][1] = sBu[n * 20 + c8 + 4 + lr];
            }
            #pragma unroll
            for (int mi = 0; mi < 2; mi++)
                #pragma unroll
                for (int ni = 0; ni < 8; ni++)
                    mma_f16(acc[mi][ni], af[mi], bf[ni][0], bf[ni][1]);
        }
        __syncthreads();
    }

    #pragma unroll
    for (int mi = 0; mi < 2; mi++) {
        int m = bm + wm + mi * 16 + lq;
        #pragma unroll
        for (int ni = 0; ni < 8; ni++) {
            int n = bn + wn + ni * 8 + lr * 2;
            float2* p0 = (float2*)(C + (size_t)m * N + n);
            float2* p1 = (float2*)(C + (size_t)(m + 8) * N + n);
            *p0 = make_float2(acc[mi][ni][0], acc[mi][ni][1]);
            *p1 = make_float2(acc[mi][ni][2], acc[mi][ni][3]);
        }
    }
}

// ---------------- fused RoPE over q and k --------------------------------------
__global__ void rope_fused_kernel(float* __restrict__ qb, float* __restrict__ kb,
                                  const float* __restrict__ cosf,
                                  const float* __restrict__ sinf,
                                  int tq, int total)
{
    int idx = blockIdx.x * blockDim.x + threadIdx.x;
    if (idx >= total) return;
    float* t; int nheads; int li;
    if (idx < tq) { t = qb; nheads = NH;  li = idx; }
    else          { t = kb; nheads = NKV; li = idx - tq; }

    int i   = li % (HD / 2);
    int h   = (li / (HD / 2)) % nheads;
    int tok = li / ((HD / 2) * nheads);
    int s   = tok % SEQ;

    float* p = t + (size_t)tok * nheads * HD + h * HD;
    float x1 = p[i];
    float x2 = p[i + HD / 2];
    float c1 = cosf[s * HD + i];
    float s1 = sinf[s * HD + i];
    float c2 = cosf[s * HD + i + HD / 2];
    float s2 = sinf[s * HD + i + HD / 2];
    p[i]          = x1 * c1 - x2 * s1;
    p[i + HD / 2] = x2 * c2 + x1 * s2;
}

// ---------------- TF32 tensor-core flash attention -----------------------------
// Epilogue writes fp16 output (K-major) for the fp16 Wo GEMM.
#define QSTR 84
#define PSTR 132

__global__ __launch_bounds__(256) void attn_tc_kernel(
    const float* __restrict__ q, const float* __restrict__ k,
    const float* __restrict__ v, __half* __restrict__ oh)
{
    extern __shared__ unsigned sm[];
    unsigned* Qs = sm;
    unsigned* Ks = Qs + 128 * QSTR;
    unsigned* Vt = Ks + 128 * QSTR;
    unsigned* Ps = Vt + 80 * PSTR;

    const int b    = blockIdx.z;
    const int h    = blockIdx.y;
    const int qt   = blockIdx.x;
    const int kvh  = h >> 2;
    const int tid  = threadIdx.x;
    const int lane = tid & 31;
    const int warp = tid >> 5;
    const int lq   = lane >> 2;
    const int lr   = lane & 3;
    const int wr   = warp * 16;
    const float scale = rsqrtf((float)HD);

    #pragma unroll
    for (int i = 0; i < 10; i++) {
        int f   = tid + i * 256;
        int row = f / 20;
        int c4  = (f % 20) * 4;
        float4 a = *(const float4*)(q + ((size_t)(b * SEQ + qt * 128 + row)) * (NH * HD)
                                      + h * HD + c4);
        Qs[row * QSTR + c4 + 0] = f2tf32(a.x);
        Qs[row * QSTR + c4 + 1] = f2tf32(a.y);
        Qs[row * QSTR + c4 + 2] = f2tf32(a.z);
        Qs[row * QSTR + c4 + 3] = f2tf32(a.w);
    }

    float oacc[10][4];
    #pragma unroll
    for (int i = 0; i < 10; i++)
        #pragma unroll
        for (int j = 0; j < 4; j++) oacc[i][j] = 0.f;
    float m0 = -INFINITY, m1 = -INFINITY;
    float l0 = 0.f, l1 = 0.f;

    const int row0 = qt * 128 + wr + lq;
    const int row1 = row0 + 8;

    for (int kt = 0; kt <= qt; kt++) {
        __syncthreads();
        #pragma unroll
        for (int i = 0; i < 10; i++) {
            int f   = tid + i * 256;
            int row = f / 20;
            int c4  = (f % 20) * 4;
            size_t g = ((size_t)(b * SEQ + kt * 128 + row)) * (NKV * HD) + kvh * HD + c4;
            float4 kk = *(const float4*)(k + g);
            Ks[row * QSTR + c4 + 0] = f2tf32(kk.x);
            Ks[row * QSTR + c4 + 1] = f2tf32(kk.y);
            Ks[row * QSTR + c4 + 2] = f2tf32(kk.z);
            Ks[row * QSTR + c4 + 3] = f2tf32(kk.w);
            float4 vv = *(const float4*)(v + g);
            Vt[(c4 + 0) * PSTR + row] = f2tf32(vv.x);
            Vt[(c4 + 1) * PSTR + row] = f2tf32(vv.y);
            Vt[(c4 + 2) * PSTR + row] = f2tf32(vv.z);
            Vt[(c4 + 3) * PSTR + row] = f2tf32(vv.w);
        }
        __syncthreads();

        float sc[16][4];
        #pragma unroll
        for (int ni = 0; ni < 16; ni++)
            #pragma unroll
            for (int j = 0; j < 4; j++) sc[ni][j] = 0.f;

        #pragma unroll
        for (int ks = 0; ks < 10; ks++) {
            unsigned af[4];
            af[0] = Qs[(wr + lq    ) * QSTR + ks * 8 + lr    ];
            af[1] = Qs[(wr + lq + 8) * QSTR + ks * 8 + lr    ];
            af[2] = Qs[(wr + lq    ) * QSTR + ks * 8 + 4 + lr];
            af[3] = Qs[(wr + lq + 8) * QSTR + ks * 8 + 4 + lr];
            #pragma unroll
            for (int ni = 0; ni < 16; ni++) {
                unsigned b0 = Ks[(ni * 8 + lq) * QSTR + ks * 8 + lr    ];
                unsigned b1 = Ks[(ni * 8 + lq) * QSTR + ks * 8 + 4 + lr];
                mma_tf32(sc[ni], af, b0, b1);
            }
        }

        const bool diag = (kt == qt);
        #pragma unroll
        for (int ni = 0; ni < 16; ni++) {
            int c = kt * 128 + ni * 8 + lr * 2;
            sc[ni][0] = (diag && c     > row0) ? -1e30f : sc[ni][0] * scale;
            sc[ni][1] = (diag && c + 1 > row0) ? -1e30f : sc[ni][1] * scale;
            sc[ni][2] = (diag && c     > row1) ? -1e30f : sc[ni][2] * scale;
            sc[ni][3] = (diag && c + 1 > row1) ? -1e30f : sc[ni][3] * scale;
        }

        float rm0 = -1e30f, rm1 = -1e30f;
        #pragma unroll
        for (int ni = 0; ni < 16; ni++) {
            rm0 = fmaxf(rm0, fmaxf(sc[ni][0], sc[ni][1]));
            rm1 = fmaxf(rm1, fmaxf(sc[ni][2], sc[ni][3]));
        }
        rm0 = fmaxf(rm0, __shfl_xor_sync(0xffffffffu, rm0, 1));
        rm0 = fmaxf(rm0, __shfl_xor_sync(0xffffffffu, rm0, 2));
        rm1 = fmaxf(rm1, __shfl_xor_sync(0xffffffffu, rm1, 1));
        rm1 = fmaxf(rm1, __shfl_xor_sync(0xffffffffu, rm1, 2));

        float m0n = fmaxf(m0, rm0);
        float m1n = fmaxf(m1, rm1);
        float a0  = __expf(m0 - m0n);
        float a1  = __expf(m1 - m1n);
        m0 = m0n; m1 = m1n;

        float rs0 = 0.f, rs1 = 0.f;
        #pragma unroll
        for (int ni = 0; ni < 16; ni++) {
            float p0 = __expf(sc[ni][0] - m0n);
            float p1 = __expf(sc[ni][1] - m0n);
            float p2 = __expf(sc[ni][2] - m1n);
            float p3 = __expf(sc[ni][3] - m1n);
            rs0 += p0 + p1;
            rs1 += p2 + p3;
            unsigned* pr0 = &Ps[(wr + lq    ) * PSTR + ni * 8 + lr * 2];
            unsigned* pr1 = &Ps[(wr + lq + 8) * PSTR + ni * 8 + lr * 2];
            pr0[0] = f2tf32(p0); pr0[1] = f2tf32(p1);
            pr1[0] = f2tf32(p2); pr1[1] = f2tf32(p3);
        }
        rs0 += __shfl_xor_sync(0xffffffffu, rs0, 1);
        rs0 += __shfl_xor_sync(0xffffffffu, rs0, 2);
        rs1 += __shfl_xor_sync(0xffffffffu, rs1, 1);
        rs1 += __shfl_xor_sync(0xffffffffu, rs1, 2);
        l0 = l0 * a0 + rs0;
        l1 = l1 * a1 + rs1;

        #pragma unroll
        for (int ni = 0; ni < 10; ni++) {
            oacc[ni][0] *= a0; oacc[ni][1] *= a0;
            oacc[ni][2] *= a1; oacc[ni][3] *= a1;
        }

        __syncwarp();

        #pragma unroll
        for (int ks = 0; ks < 16; ks++) {
            unsigned af[4];
            af[0] = Ps[(wr + lq    ) * PSTR + ks * 8 + lr    ];
            af[1] = Ps[(wr + lq + 8) * PSTR + ks * 8 + lr    ];
            af[2] = Ps[(wr + lq    ) * PSTR + ks * 8 + 4 + lr];
            af[3] = Ps[(wr + lq + 8) * PSTR + ks * 8 + 4 + lr];
            #pragma unroll
            for (int ni = 0; ni < 10; ni++) {
                unsigned b0 = Vt[(ni * 8 + lq) * PSTR + ks * 8 + lr    ];
                unsigned b1 = Vt[(ni * 8 + lq) * PSTR + ks * 8 + 4 + lr];
                mma_tf32(oacc[ni], af, b0, b1);
            }
        }
    }

    // epilogue: fp16 output (K-major) feeds the fp16 Wo GEMM
    const float inv0 = 1.0f / l0;
    const float inv1 = 1.0f / l1;
    #pragma unroll
    for (int ni = 0; ni < 10; ni++) {
        int c = ni * 8 + lr * 2;
        __half2* p0 = (__half2*)(oh + (size_t)(b * SEQ + row0) * (NH * HD) + h * HD + c);
        __half2* p1 = (__half2*)(oh + (size_t)(b * SEQ + row1) * (NH * HD) + h * HD + c);
        *p0 = __floats2half2_rn(oacc[ni][0] * inv0, oacc[ni][1] * inv0);
        *p1 = __floats2half2_rn(oacc[ni][2] * inv1, oacc[ni][3] * inv1);
    }
}

// ---------------- launch --------------------------------------------------------
extern "C" void kernel_launch(void* const* d_in, const int* in_sizes, int n_in,
                              void* d_out, int out_size)
{
    const float* x    = (const float*)d_in[0];
    const float* cosf = (const float*)d_in[1];
    const float* sinf = (const float*)d_in[2];
    const float* Wq   = (const float*)d_in[3];
    const float* Wk   = (const float*)d_in[4];
    const float* Wv   = (const float*)d_in[5];
    const float* Wo   = (const float*)d_in[6];
    float* out = (float*)d_out;

    float *qb, *kb, *vb;
    __half *ohb, *xh, *wqh, *wkh, *wvh, *woh;
    cudaGetSymbolAddress((void**)&qb, g_q);
    cudaGetSymbolAddress((void**)&kb, g_k);
    cudaGetSymbolAddress((void**)&vb, g_v);
    cudaGetSymbolAddress((void**)&ohb, g_oh);
    cudaGetSymbolAddress((void**)&xh, g_xh);
    cudaGetSymbolAddress((void**)&wqh, g_wqh);
    cudaGetSymbolAddress((void**)&wkh, g_wkh);
    cudaGetSymbolAddress((void**)&wvh, g_wvh);
    cudaGetSymbolAddress((void**)&woh, g_woh);

    // prep: x -> half (K-major), weights -> transposed [N,K] half
    {
        int n8 = M_TOK * HIDDEN / 8;
        f2h_kernel<<<(n8 + 255) / 256, 256>>>(x, xh, n8);
        dim3 blk(32, 8);
        f2h_transpose_kernel<<<dim3((NH * HD) / 32, HIDDEN / 32), blk>>>(Wq, wqh, HIDDEN, NH * HD);
        f2h_transpose_kernel<<<dim3((NKV * HD) / 32, HIDDEN / 32), blk>>>(Wk, wkh, HIDDEN, NKV * HD);
        f2h_transpose_kernel<<<dim3((NKV * HD) / 32, HIDDEN / 32), blk>>>(Wv, wvh, HIDDEN, NKV * HD);
        f2h_transpose_kernel<<<dim3(HIDDEN / 32, (NH * HD) / 32), blk>>>(Wo, woh, NH * HD, HIDDEN);
    }

    cudaFuncSetAttribute(h16_gemm3_kernel,
                         cudaFuncAttributeMaxDynamicSharedMemorySize, GEMM_SMEM);

    // fused Q/K/V projections (fp16 mma)
    {
        dim3 g(30, M_TOK / 128);
        h16_gemm3_kernel<<<g, 256, GEMM_SMEM>>>(
            xh,
            wqh, qb, NH * HD, 20,
            wkh, kb, NKV * HD, 25,
            wvh, vb, NKV * HD,
            M_TOK, HIDDEN);
    }

    // fused RoPE
    {
        int tq = M_TOK * NH * (HD / 2);
        int tk = M_TOK * NKV * (HD / 2);
        int tot = tq + tk;
        rope_fused_kernel<<<(tot + 255) / 256, 256>>>(qb, kb, cosf, sinf, tq, tot);
    }

    // attention (tf32 mma flash), fp16 output
    {
        static const int smem_bytes =
            (128 * QSTR + 128 * QSTR + 80 * PSTR + 128 * PSTR) * 4;
        cudaFuncSetAttribute(attn_tc_kernel,
                             cudaFuncAttributeMaxDynamicSharedMemorySize, smem_bytes);
        dim3 ga(SEQ / 128, NH, BATCH);
        attn_tc_kernel<<<ga, 256, smem_bytes>>>(qb, kb, vb, ohb);
    }

    // output projection (fp16 mma)
    {
        dim3 go(HIDDEN / 128, M_TOK / 128);
        h16_gemm3_kernel<<<go, 256, GEMM_SMEM>>>(
            ohb,
            woh, out, HIDDEN, 20,
            woh, out, HIDDEN, 20,
            woh, out, HIDDEN,
            M_TOK, HIDDEN);
    }
}

// round 9
// speedup vs baseline: 1.4379x; 1.1374x over previous
#include <cuda_runtime.h>
#include <cuda_fp16.h>
#include <math.h>
#include <stdint.h>

#define HIDDEN 2560
#define NH 32
#define NKV 8
#define HD 80
#define BATCH 2
#define SEQ 2048
#define M_TOK (BATCH * SEQ)   // 4096

// ---------------- scratch (static device globals; no runtime alloc) ----------
__device__ float  g_q[M_TOK * NH * HD];
__device__ float  g_k[M_TOK * NKV * HD];
__device__ float  g_v[M_TOK * NKV * HD];
__device__ __half g_oh[M_TOK * NH * HD];       // attn out, half, K-major
__device__ __half g_xh[M_TOK * HIDDEN];        // x rounded to half
__device__ __half g_wqh[HIDDEN * NH * HD];     // weights: transposed [N,K] half
__device__ __half g_wkh[HIDDEN * NKV * HD];
__device__ __half g_wvh[HIDDEN * NKV * HD];
__device__ __half g_woh[NH * HD * HIDDEN];

__device__ __forceinline__ void mma_f16(float* c, const unsigned* a,
                                        unsigned b0, unsigned b1) {
    asm volatile(
        "mma.sync.aligned.m16n8k16.row.col.f32.f16.f16.f32 "
        "{%0,%1,%2,%3}, {%4,%5,%6,%7}, {%8,%9}, {%0,%1,%2,%3};"
        : "+f"(c[0]), "+f"(c[1]), "+f"(c[2]), "+f"(c[3])
        : "r"(a[0]), "r"(a[1]), "r"(a[2]), "r"(a[3]),
          "r"(b0), "r"(b1));
}

__device__ __forceinline__ unsigned packh2(float x, float y) {
    __half2 h = __floats2half2_rn(x, y);
    return *(unsigned*)&h;
}

__device__ __forceinline__ void cp_async16(void* smem_ptr, const void* gptr) {
    unsigned saddr = (unsigned)__cvta_generic_to_shared(smem_ptr);
    asm volatile("cp.async.cg.shared.global [%0], [%1], 16;\n"
                 :: "r"(saddr), "l"(gptr));
}
__device__ __forceinline__ void cp_commit() {
    asm volatile("cp.async.commit_group;\n");
}
__device__ __forceinline__ void cp_wait0() {
    asm volatile("cp.async.wait_group 0;\n");
}

// ---------------- prep: fp32 -> fp16, same layout ------------------------------
__global__ void f2h_kernel(const float* __restrict__ in,
                           __half* __restrict__ out, int n8)
{
    int i = blockIdx.x * blockDim.x + threadIdx.x;
    if (i >= n8) return;
    const float4* ip = (const float4*)in + (size_t)i * 2;
    float4 a = ip[0], b = ip[1];
    uint4 o;
    o.x = packh2(a.x, a.y); o.y = packh2(a.z, a.w);
    o.z = packh2(b.x, b.y); o.w = packh2(b.z, b.w);
    *((uint4*)out + i) = o;
}

// ---------------- prep: transpose [K,N] fp32 -> [N,K] fp16 ---------------------
__global__ void f2h_transpose_kernel(const float* __restrict__ in,
                                     __half* __restrict__ out,
                                     int Kdim, int Ndim)
{
    __shared__ float t[32][33];
    int n0 = blockIdx.x * 32, k0 = blockIdx.y * 32;
    #pragma unroll
    for (int j = 0; j < 4; j++)
        t[threadIdx.y + j * 8][threadIdx.x] =
            in[(size_t)(k0 + threadIdx.y + j * 8) * Ndim + n0 + threadIdx.x];
    __syncthreads();
    #pragma unroll
    for (int j = 0; j < 4; j++)
        out[(size_t)(n0 + threadIdx.y + j * 8) * Kdim + k0 + threadIdx.x] =
            __float2half_rn(t[threadIdx.x][threadIdx.y + j * 8]);
}

// ---------------- pipelined FP16 GEMM, up to 3 output segments -----------------
#define HSTR 40                         // halves per smem row
#define TILEH (128 * HSTR)              // halves per tile = 5120
#define STGH  (2 * TILEH)
#define GEMM_SMEM (2 * STGH * 2)        // 40960 bytes

__global__ __launch_bounds__(256) void h16_gemm3_kernel(
    const __half* __restrict__ A,
    const __half* __restrict__ B0, float* __restrict__ C0, int N0, int xs0,
    const __half* __restrict__ B1, float* __restrict__ C1, int N1, int xs1,
    const __half* __restrict__ B2, float* __restrict__ C2, int N2,
    int M, int K)
{
    extern __shared__ __half smh[];

    const int bx = blockIdx.x;
    const __half* B; float* C; int N; int bxl;
    if (bx < xs0)      { B = B0; C = C0; N = N0; bxl = bx; }
    else if (bx < xs1) { B = B1; C = C1; N = N1; bxl = bx - xs0; }
    else               { B = B2; C = C2; N = N2; bxl = bx - xs1; }

    const int tid  = threadIdx.x;
    const int lane = tid & 31;
    const int warp = tid >> 5;
    const int wm   = (warp & 3) * 32;
    const int wn   = (warp >> 2) * 64;
    const int bm   = blockIdx.y * 128;
    const int bn   = bxl * 128;
    const int lq   = lane >> 2;
    const int lr   = lane & 3;

    const int cr = tid >> 2;
    const int cc = tid & 3;

    float acc[2][8][4];
    #pragma unroll
    for (int i = 0; i < 2; i++)
        #pragma unroll
        for (int j = 0; j < 8; j++)
            #pragma unroll
            for (int r = 0; r < 4; r++) acc[i][j][r] = 0.f;

    const int T = K / 32;

    {
        __half* sA = smh;
        __half* sB = smh + TILEH;
        #pragma unroll
        for (int i = 0; i < 2; i++) {
            int r = cr + i * 64;
            cp_async16(sA + r * HSTR + cc * 8, A + (size_t)(bm + r) * K + cc * 8);
            cp_async16(sB + r * HSTR + cc * 8, B + (size_t)(bn + r) * K + cc * 8);
        }
        cp_commit();
    }

    for (int t = 0; t < T; t++) {
        cp_wait0();
        __syncthreads();

        if (t + 1 < T) {
            __half* sA = smh + ((t + 1) & 1) * STGH;
            __half* sB = sA + TILEH;
            int k0 = (t + 1) * 32;
            #pragma unroll
            for (int i = 0; i < 2; i++) {
                int r = cr + i * 64;
                cp_async16(sA + r * HSTR + cc * 8,
                           A + (size_t)(bm + r) * K + k0 + cc * 8);
                cp_async16(sB + r * HSTR + cc * 8,
                           B + (size_t)(bn + r) * K + k0 + cc * 8);
            }
        }
        cp_commit();

        const unsigned* sAu = (const unsigned*)(smh + (t & 1) * STGH);
        const unsigned* sBu = sAu + TILEH / 2;
        #pragma unroll
        for (int ks = 0; ks < 2; ks++) {
            const int c8 = ks * 8;
            unsigned af[2][4];
            #pragma unroll
            for (int mi = 0; mi < 2; mi++) {
                int m = wm + mi * 16 + lq;
                af[mi][0] = sAu[(m    ) * 20 + c8 + lr    ];
                af[mi][1] = sAu[(m + 8) * 20 + c8 + lr    ];
                af[mi][2] = sAu[(m    ) * 20 + c8 + 4 + lr];
                af[mi][3] = sAu[(m + 8) * 20 + c8 + 4 + lr];
            }
            unsigned bf[8][2];
            #pragma unroll
            for (int ni = 0; ni < 8; ni++) {
                int n = wn + ni * 8 + lq;
                bf[ni][0] = sBu[n * 20 + c8 + lr    ];
                bf[ni][1] = sBu[n * 20 + c8 + 4 + lr];
            }
            #pragma unroll
            for (int mi = 0; mi < 2; mi++)
                #pragma unroll
                for (int ni = 0; ni < 8; ni++)
                    mma_f16(acc[mi][ni], af[mi], bf[ni][0], bf[ni][1]);
        }
        __syncthreads();
    }

    #pragma unroll
    for (int mi = 0; mi < 2; mi++) {
        int m = bm + wm + mi * 16 + lq;
        #pragma unroll
        for (int ni = 0; ni < 8; ni++) {
            int n = bn + wn + ni * 8 + lr * 2;
            float2* p0 = (float2*)(C + (size_t)m * N + n);
            float2* p1 = (float2*)(C + (size_t)(m + 8) * N + n);
            *p0 = make_float2(acc[mi][ni][0], acc[mi][ni][1]);
            *p1 = make_float2(acc[mi][ni][2], acc[mi][ni][3]);
        }
    }
}

// ---------------- fused RoPE over q and k --------------------------------------
__global__ void rope_fused_kernel(float* __restrict__ qb, float* __restrict__ kb,
                                  const float* __restrict__ cosf,
                                  const float* __restrict__ sinf,
                                  int tq, int total)
{
    int idx = blockIdx.x * blockDim.x + threadIdx.x;
    if (idx >= total) return;
    float* t; int nheads; int li;
    if (idx < tq) { t = qb; nheads = NH;  li = idx; }
    else          { t = kb; nheads = NKV; li = idx - tq; }

    int i   = li % (HD / 2);
    int h   = (li / (HD / 2)) % nheads;
    int tok = li / ((HD / 2) * nheads);
    int s   = tok % SEQ;

    float* p = t + (size_t)tok * nheads * HD + h * HD;
    float x1 = p[i];
    float x2 = p[i + HD / 2];
    float c1 = cosf[s * HD + i];
    float s1 = sinf[s * HD + i];
    float c2 = cosf[s * HD + i + HD / 2];
    float s2 = sinf[s * HD + i + HD / 2];
    p[i]          = x1 * c1 - x2 * s1;
    p[i + HD / 2] = x2 * c2 + x1 * s2;
}

// ---------------- FP16 tensor-core flash attention -----------------------------
// All smem tiles fp16. Word strides: Q/K rows 44 words, Vt/Ps rows 76 words
// (both ==12 mod 32 -> conflict-free fragment LDS). m16n8k16 mma, fp32 accum.
#define QW 44                 // words per Q/K row
#define PW 76                 // words per Vt/Ps row
#define ATT_WORDS (128 * QW + 128 * QW + 80 * PW + 128 * PW)   // 27072 words
#define ATT_SMEM  (ATT_WORDS * 4)                              // 108288 bytes

__global__ __launch_bounds__(256) void attn_h16_kernel(
    const float* __restrict__ q, const float* __restrict__ k,
    const float* __restrict__ v, __half* __restrict__ oh)
{
    extern __shared__ unsigned sw[];
    unsigned* Qw = sw;                     // [128][44]
    unsigned* Kw = Qw + 128 * QW;          // [128][44]
    unsigned* Vw = Kw + 128 * QW;          // [80][76]   V^T: [d][key pairs]
    unsigned* Pw = Vw + 80 * PW;           // [128][76]
    __half* Vh = (__half*)Vw;

    const int b    = blockIdx.z;
    const int h    = blockIdx.y;
    const int qt   = blockIdx.x;
    const int kvh  = h >> 2;
    const int tid  = threadIdx.x;
    const int lane = tid & 31;
    const int warp = tid >> 5;
    const int lq   = lane >> 2;
    const int lr   = lane & 3;
    const int wr   = warp * 16;
    const float scale = rsqrtf((float)HD);

    // ---- load Q tile (128 x 80) -> half ----
    #pragma unroll
    for (int i = 0; i < 10; i++) {
        int f   = tid + i * 256;
        int row = f / 20;
        int cw  = (f % 20) * 2;            // word col (pairs of halves)
        float4 a = *(const float4*)(q + ((size_t)(b * SEQ + qt * 128 + row)) * (NH * HD)
                                      + h * HD + cw * 2);
        Qw[row * QW + cw    ] = packh2(a.x, a.y);
        Qw[row * QW + cw + 1] = packh2(a.z, a.w);
    }

    float oacc[10][4];
    #pragma unroll
    for (int i = 0; i < 10; i++)
        #pragma unroll
        for (int j = 0; j < 4; j++) oacc[i][j] = 0.f;
    float m0 = -INFINITY, m1 = -INFINITY;
    float l0 = 0.f, l1 = 0.f;

    const int row0 = qt * 128 + wr + lq;
    const int row1 = row0 + 8;

    for (int kt = 0; kt <= qt; kt++) {
        __syncthreads();
        // ---- load K (128x80 half) and V^T (80x128 half) ----
        #pragma unroll
        for (int i = 0; i < 10; i++) {
            int f   = tid + i * 256;
            int row = f / 20;
            int cw  = (f % 20) * 2;
            int c4  = cw * 2;
            size_t g = ((size_t)(b * SEQ + kt * 128 + row)) * (NKV * HD) + kvh * HD + c4;
            float4 kk = *(const float4*)(k + g);
            Kw[row * QW + cw    ] = packh2(kk.x, kk.y);
            Kw[row * QW + cw + 1] = packh2(kk.z, kk.w);
            float4 vv = *(const float4*)(v + g);
            Vh[(c4 + 0) * (2 * PW) + row] = __float2half_rn(vv.x);
            Vh[(c4 + 1) * (2 * PW) + row] = __float2half_rn(vv.y);
            Vh[(c4 + 2) * (2 * PW) + row] = __float2half_rn(vv.z);
            Vh[(c4 + 3) * (2 * PW) + row] = __float2half_rn(vv.w);
        }
        __syncthreads();

        // ---- QK^T: S[16 x 128] per warp, 5 k-steps of 16 over HD=80 ----
        float sc[16][4];
        #pragma unroll
        for (int ni = 0; ni < 16; ni++)
            #pragma unroll
            for (int j = 0; j < 4; j++) sc[ni][j] = 0.f;

        #pragma unroll
        for (int ks = 0; ks < 5; ks++) {
            unsigned af[4];
            af[0] = Qw[(wr + lq    ) * QW + ks * 8 + lr    ];
            af[1] = Qw[(wr + lq + 8) * QW + ks * 8 + lr    ];
            af[2] = Qw[(wr + lq    ) * QW + ks * 8 + 4 + lr];
            af[3] = Qw[(wr + lq + 8) * QW + ks * 8 + 4 + lr];
            #pragma unroll
            for (int ni = 0; ni < 16; ni++) {
                unsigned b0 = Kw[(ni * 8 + lq) * QW + ks * 8 + lr    ];
                unsigned b1 = Kw[(ni * 8 + lq) * QW + ks * 8 + 4 + lr];
                mma_f16(sc[ni], af, b0, b1);
            }
        }

        // ---- scale + causal mask ----
        const bool diag = (kt == qt);
        #pragma unroll
        for (int ni = 0; ni < 16; ni++) {
            int c = kt * 128 + ni * 8 + lr * 2;
            sc[ni][0] = (diag && c     > row0) ? -1e30f : sc[ni][0] * scale;
            sc[ni][1] = (diag && c + 1 > row0) ? -1e30f : sc[ni][1] * scale;
            sc[ni][2] = (diag && c     > row1) ? -1e30f : sc[ni][2] * scale;
            sc[ni][3] = (diag && c + 1 > row1) ? -1e30f : sc[ni][3] * scale;
        }

        // ---- online softmax ----
        float rm0 = -1e30f, rm1 = -1e30f;
        #pragma unroll
        for (int ni = 0; ni < 16; ni++) {
            rm0 = fmaxf(rm0, fmaxf(sc[ni][0], sc[ni][1]));
            rm1 = fmaxf(rm1, fmaxf(sc[ni][2], sc[ni][3]));
        }
        rm0 = fmaxf(rm0, __shfl_xor_sync(0xffffffffu, rm0, 1));
        rm0 = fmaxf(rm0, __shfl_xor_sync(0xffffffffu, rm0, 2));
        rm1 = fmaxf(rm1, __shfl_xor_sync(0xffffffffu, rm1, 1));
        rm1 = fmaxf(rm1, __shfl_xor_sync(0xffffffffu, rm1, 2));

        float m0n = fmaxf(m0, rm0);
        float m1n = fmaxf(m1, rm1);
        float a0  = __expf(m0 - m0n);
        float a1  = __expf(m1 - m1n);
        m0 = m0n; m1 = m1n;

        float rs0 = 0.f, rs1 = 0.f;
        #pragma unroll
        for (int ni = 0; ni < 16; ni++) {
            float p0 = __expf(sc[ni][0] - m0n);
            float p1 = __expf(sc[ni][1] - m0n);
            float p2 = __expf(sc[ni][2] - m1n);
            float p3 = __expf(sc[ni][3] - m1n);
            rs0 += p0 + p1;
            rs1 += p2 + p3;
            Pw[(wr + lq    ) * PW + ni * 4 + lr] = packh2(p0, p1);
            Pw[(wr + lq + 8) * PW + ni * 4 + lr] = packh2(p2, p3);
        }
        rs0 += __shfl_xor_sync(0xffffffffu, rs0, 1);
        rs0 += __shfl_xor_sync(0xffffffffu, rs0, 2);
        rs1 += __shfl_xor_sync(0xffffffffu, rs1, 1);
        rs1 += __shfl_xor_sync(0xffffffffu, rs1, 2);
        l0 = l0 * a0 + rs0;
        l1 = l1 * a1 + rs1;

        #pragma unroll
        for (int ni = 0; ni < 10; ni++) {
            oacc[ni][0] *= a0; oacc[ni][1] *= a0;
            oacc[ni][2] *= a1; oacc[ni][3] *= a1;
        }

        __syncwarp();   // Ps rows are warp-private

        // ---- PV: O[16 x 80] += P[16 x 128] @ V[128 x 80], 8 k-steps ----
        #pragma unroll
        for (int ks = 0; ks < 8; ks++) {
            unsigned af[4];
            af[0] = Pw[(wr + lq    ) * PW + ks * 8 + lr    ];
            af[1] = Pw[(wr + lq + 8) * PW + ks * 8 + lr    ];
            af[2] = Pw[(wr + lq    ) * PW + ks * 8 + 4 + lr];
            af[3] = Pw[(wr + lq + 8) * PW + ks * 8 + 4 + lr];
            #pragma unroll
            for (int ni = 0; ni < 10; ni++) {
                unsigned b0 = Vw[(ni * 8 + lq) * PW + ks * 8 + lr    ];
                unsigned b1 = Vw[(ni * 8 + lq) * PW + ks * 8 + 4 + lr];
                mma_f16(oacc[ni], af, b0, b1);
            }
        }
    }

    // ---- epilogue: fp16 output feeds the fp16 Wo GEMM ----
    const float inv0 = 1.0f / l0;
    const float inv1 = 1.0f / l1;
    #pragma unroll
    for (int ni = 0; ni < 10; ni++) {
        int c = ni * 8 + lr * 2;
        __half2* p0 = (__half2*)(oh + (size_t)(b * SEQ + row0) * (NH * HD) + h * HD + c);
        __half2* p1 = (__half2*)(oh + (size_t)(b * SEQ + row1) * (NH * HD) + h * HD + c);
        *p0 = __floats2half2_rn(oacc[ni][0] * inv0, oacc[ni][1] * inv0);
        *p1 = __floats2half2_rn(oacc[ni][2] * inv1, oacc[ni][3] * inv1);
    }
}

// ---------------- launch --------------------------------------------------------
extern "C" void kernel_launch(void* const* d_in, const int* in_sizes, int n_in,
                              void* d_out, int out_size)
{
    const float* x    = (const float*)d_in[0];
    const float* cosf = (const float*)d_in[1];
    const float* sinf = (const float*)d_in[2];
    const float* Wq   = (const float*)d_in[3];
    const float* Wk   = (const float*)d_in[4];
    const float* Wv   = (const float*)d_in[5];
    const float* Wo   = (const float*)d_in[6];
    float* out = (float*)d_out;

    float *qb, *kb, *vb;
    __half *ohb, *xh, *wqh, *wkh, *wvh, *woh;
    cudaGetSymbolAddress((void**)&qb, g_q);
    cudaGetSymbolAddress((void**)&kb, g_k);
    cudaGetSymbolAddress((void**)&vb, g_v);
    cudaGetSymbolAddress((void**)&ohb, g_oh);
    cudaGetSymbolAddress((void**)&xh, g_xh);
    cudaGetSymbolAddress((void**)&wqh, g_wqh);
    cudaGetSymbolAddress((void**)&wkh, g_wkh);
    cudaGetSymbolAddress((void**)&wvh, g_wvh);
    cudaGetSymbolAddress((void**)&woh, g_woh);

    // prep: x -> half, weights -> transposed [N,K] half
    {
        int n8 = M_TOK * HIDDEN / 8;
        f2h_kernel<<<(n8 + 255) / 256, 256>>>(x, xh, n8);
        dim3 blk(32, 8);
        f2h_transpose_kernel<<<dim3((NH * HD) / 32, HIDDEN / 32), blk>>>(Wq, wqh, HIDDEN, NH * HD);
        f2h_transpose_kernel<<<dim3((NKV * HD) / 32, HIDDEN / 32), blk>>>(Wk, wkh, HIDDEN, NKV * HD);
        f2h_transpose_kernel<<<dim3((NKV * HD) / 32, HIDDEN / 32), blk>>>(Wv, wvh, HIDDEN, NKV * HD);
        f2h_transpose_kernel<<<dim3(HIDDEN / 32, (NH * HD) / 32), blk>>>(Wo, woh, NH * HD, HIDDEN);
    }

    cudaFuncSetAttribute(h16_gemm3_kernel,
                         cudaFuncAttributeMaxDynamicSharedMemorySize, GEMM_SMEM);

    // fused Q/K/V projections (fp16 mma)
    {
        dim3 g(30, M_TOK / 128);
        h16_gemm3_kernel<<<g, 256, GEMM_SMEM>>>(
            xh,
            wqh, qb, NH * HD, 20,
            wkh, kb, NKV * HD, 25,
            wvh, vb, NKV * HD,
            M_TOK, HIDDEN);
    }

    // fused RoPE
    {
        int tq = M_TOK * NH * (HD / 2);
        int tk = M_TOK * NKV * (HD / 2);
        int tot = tq + tk;
        rope_fused_kernel<<<(tot + 255) / 256, 256>>>(qb, kb, cosf, sinf, tq, tot);
    }

    // attention (fp16 mma flash)
    {
        cudaFuncSetAttribute(attn_h16_kernel,
                             cudaFuncAttributeMaxDynamicSharedMemorySize, ATT_SMEM);
        dim3 ga(SEQ / 128, NH, BATCH);
        attn_h16_kernel<<<ga, 256, ATT_SMEM>>>(qb, kb, vb, ohb);
    }

    // output projection (fp16 mma)
    {
        dim3 go(HIDDEN / 128, M_TOK / 128);
        h16_gemm3_kernel<<<go, 256, GEMM_SMEM>>>(
            ohb,
            woh, out, HIDDEN, 20,
            woh, out, HIDDEN, 20,
            woh, out, HIDDEN,
            M_TOK, HIDDEN);
    }
}

// round 10
// speedup vs baseline: 1.5547x; 1.0813x over previous
#include <cuda_runtime.h>
#include <cuda_fp16.h>
#include <math.h>
#include <stdint.h>

#define HIDDEN 2560
#define NH 32
#define NKV 8
#define HD 80
#define BATCH 2
#define SEQ 2048
#define M_TOK (BATCH * SEQ)   // 4096

// ---------------- scratch (static device globals; no runtime alloc) ----------
__device__ float  g_q[M_TOK * NH * HD];
__device__ float  g_k[M_TOK * NKV * HD];
__device__ float  g_v[M_TOK * NKV * HD];
__device__ __half g_oh[M_TOK * NH * HD];       // attn out, half, K-major
__device__ __half g_xh[M_TOK * HIDDEN];        // x rounded to half
__device__ __half g_wqh[HIDDEN * NH * HD];     // weights: transposed [N,K] half
__device__ __half g_wkh[HIDDEN * NKV * HD];
__device__ __half g_wvh[HIDDEN * NKV * HD];
__device__ __half g_woh[NH * HD * HIDDEN];

__device__ __forceinline__ void mma_f16(float* c, const unsigned* a,
                                        unsigned b0, unsigned b1) {
    asm volatile(
        "mma.sync.aligned.m16n8k16.row.col.f32.f16.f16.f32 "
        "{%0,%1,%2,%3}, {%4,%5,%6,%7}, {%8,%9}, {%0,%1,%2,%3};"
        : "+f"(c[0]), "+f"(c[1]), "+f"(c[2]), "+f"(c[3])
        : "r"(a[0]), "r"(a[1]), "r"(a[2]), "r"(a[3]),
          "r"(b0), "r"(b1));
}

__device__ __forceinline__ void ldsm_x4(unsigned& r0, unsigned& r1,
                                        unsigned& r2, unsigned& r3,
                                        uint32_t addr) {
    asm volatile("ldmatrix.sync.aligned.m8n8.x4.shared.b16 {%0,%1,%2,%3}, [%4];"
                 : "=r"(r0), "=r"(r1), "=r"(r2), "=r"(r3) : "r"(addr));
}

__device__ __forceinline__ unsigned packh2(float x, float y) {
    __half2 h = __floats2half2_rn(x, y);
    return *(unsigned*)&h;
}

__device__ __forceinline__ void cp_async16(void* smem_ptr, const void* gptr) {
    unsigned saddr = (unsigned)__cvta_generic_to_shared(smem_ptr);
    asm volatile("cp.async.cg.shared.global [%0], [%1], 16;\n"
                 :: "r"(saddr), "l"(gptr));
}
__device__ __forceinline__ void cp_commit() {
    asm volatile("cp.async.commit_group;\n");
}
__device__ __forceinline__ void cp_wait0() {
    asm volatile("cp.async.wait_group 0;\n");
}

// ---------------- prep: fp32 -> fp16, same layout ------------------------------
__global__ void f2h_kernel(const float* __restrict__ in,
                           __half* __restrict__ out, int n8)
{
    int i = blockIdx.x * blockDim.x + threadIdx.x;
    if (i >= n8) return;
    const float4* ip = (const float4*)in + (size_t)i * 2;
    float4 a = ip[0], b = ip[1];
    uint4 o;
    o.x = packh2(a.x, a.y); o.y = packh2(a.z, a.w);
    o.z = packh2(b.x, b.y); o.w = packh2(b.z, b.w);
    *((uint4*)out + i) = o;
}

// ---------------- prep: transpose [K,N] fp32 -> [N,K] fp16 ---------------------
__global__ void f2h_transpose_kernel(const float* __restrict__ in,
                                     __half* __restrict__ out,
                                     int Kdim, int Ndim)
{
    __shared__ float t[32][33];
    int n0 = blockIdx.x * 32, k0 = blockIdx.y * 32;
    #pragma unroll
    for (int j = 0; j < 4; j++)
        t[threadIdx.y + j * 8][threadIdx.x] =
            in[(size_t)(k0 + threadIdx.y + j * 8) * Ndim + n0 + threadIdx.x];
    __syncthreads();
    #pragma unroll
    for (int j = 0; j < 4; j++)
        out[(size_t)(n0 + threadIdx.y + j * 8) * Kdim + k0 + threadIdx.x] =
            __float2half_rn(t[threadIdx.x][threadIdx.y + j * 8]);
}

// ---------------- pipelined FP16 GEMM (ldmatrix frags), 3 segments -------------
#define HSTR 40                         // halves per smem row (80 bytes)
#define TILEH (128 * HSTR)              // halves per tile = 5120
#define STGH  (2 * TILEH)
#define GEMM_SMEM (2 * STGH * 2)        // 40960 bytes

__global__ __launch_bounds__(256) void h16_gemm3_kernel(
    const __half* __restrict__ A,
    const __half* __restrict__ B0, float* __restrict__ C0, int N0, int xs0,
    const __half* __restrict__ B1, float* __restrict__ C1, int N1, int xs1,
    const __half* __restrict__ B2, float* __restrict__ C2, int N2,
    int M, int K)
{
    extern __shared__ __half smh[];
    const uint32_t sbase = (uint32_t)__cvta_generic_to_shared(smh);

    const int bx = blockIdx.x;
    const __half* B; float* C; int N; int bxl;
    if (bx < xs0)      { B = B0; C = C0; N = N0; bxl = bx; }
    else if (bx < xs1) { B = B1; C = C1; N = N1; bxl = bx - xs0; }
    else               { B = B2; C = C2; N = N2; bxl = bx - xs1; }

    const int tid  = threadIdx.x;
    const int lane = tid & 31;
    const int warp = tid >> 5;
    const int wm   = (warp & 3) * 32;
    const int wn   = (warp >> 2) * 64;
    const int bm   = blockIdx.y * 128;
    const int bn   = bxl * 128;
    const int lq   = lane >> 2;
    const int lr   = lane & 3;

    // ldmatrix lane->row/word maps
    const int arow_l = (lane & 7) + ((lane >> 3) & 1) * 8;
    const int awrd_l = (lane >> 4) * 4;
    const int brow_l = (lane & 7) + (lane >> 4) * 8;
    const int bwrd_l = ((lane >> 3) & 1) * 4;

    const int cr = tid >> 2;
    const int cc = tid & 3;

    float acc[2][8][4];
    #pragma unroll
    for (int i = 0; i < 2; i++)
        #pragma unroll
        for (int j = 0; j < 8; j++)
            #pragma unroll
            for (int r = 0; r < 4; r++) acc[i][j][r] = 0.f;

    const int T = K / 32;

    {
        __half* sA = smh;
        __half* sB = smh + TILEH;
        #pragma unroll
        for (int i = 0; i < 2; i++) {
            int r = cr + i * 64;
            cp_async16(sA + r * HSTR + cc * 8, A + (size_t)(bm + r) * K + cc * 8);
            cp_async16(sB + r * HSTR + cc * 8, B + (size_t)(bn + r) * K + cc * 8);
        }
        cp_commit();
    }

    for (int t = 0; t < T; t++) {
        cp_wait0();
        __syncthreads();

        if (t + 1 < T) {
            __half* sA = smh + ((t + 1) & 1) * STGH;
            __half* sB = sA + TILEH;
            int k0 = (t + 1) * 32;
            #pragma unroll
            for (int i = 0; i < 2; i++) {
                int r = cr + i * 64;
                cp_async16(sA + r * HSTR + cc * 8,
                           A + (size_t)(bm + r) * K + k0 + cc * 8);
                cp_async16(sB + r * HSTR + cc * 8,
                           B + (size_t)(bn + r) * K + k0 + cc * 8);
            }
        }
        cp_commit();

        const uint32_t stA = sbase + ((t & 1) * STGH) * 2;
        const uint32_t stB = stA + TILEH * 2;
        #pragma unroll
        for (int ks = 0; ks < 2; ks++) {
            const int c8 = ks * 8;
            unsigned af[2][4];
            #pragma unroll
            for (int mi = 0; mi < 2; mi++)
                ldsm_x4(af[mi][0], af[mi][1], af[mi][2], af[mi][3],
                        stA + (uint32_t)(wm + mi * 16 + arow_l) * 80
                            + (uint32_t)(c8 + awrd_l) * 4);
            unsigned bf[8][2];
            #pragma unroll
            for (int nb = 0; nb < 8; nb += 2)
                ldsm_x4(bf[nb][0], bf[nb][1], bf[nb + 1][0], bf[nb + 1][1],
                        stB + (uint32_t)(wn + nb * 8 + brow_l) * 80
                            + (uint32_t)(c8 + bwrd_l) * 4);
            #pragma unroll
            for (int mi = 0; mi < 2; mi++)
                #pragma unroll
                for (int ni = 0; ni < 8; ni++)
                    mma_f16(acc[mi][ni], af[mi], bf[ni][0], bf[ni][1]);
        }
        __syncthreads();
    }

    #pragma unroll
    for (int mi = 0; mi < 2; mi++) {
        int m = bm + wm + mi * 16 + lq;
        #pragma unroll
        for (int ni = 0; ni < 8; ni++) {
            int n = bn + wn + ni * 8 + lr * 2;
            float2* p0 = (float2*)(C + (size_t)m * N + n);
            float2* p1 = (float2*)(C + (size_t)(m + 8) * N + n);
            *p0 = make_float2(acc[mi][ni][0], acc[mi][ni][1]);
            *p1 = make_float2(acc[mi][ni][2], acc[mi][ni][3]);
        }
    }
}

// ---------------- fused RoPE over q and k --------------------------------------
__global__ void rope_fused_kernel(float* __restrict__ qb, float* __restrict__ kb,
                                  const float* __restrict__ cosf,
                                  const float* __restrict__ sinf,
                                  int tq, int total)
{
    int idx = blockIdx.x * blockDim.x + threadIdx.x;
    if (idx >= total) return;
    float* t; int nheads; int li;
    if (idx < tq) { t = qb; nheads = NH;  li = idx; }
    else          { t = kb; nheads = NKV; li = idx - tq; }

    int i   = li % (HD / 2);
    int h   = (li / (HD / 2)) % nheads;
    int tok = li / ((HD / 2) * nheads);
    int s   = tok % SEQ;

    float* p = t + (size_t)tok * nheads * HD + h * HD;
    float x1 = p[i];
    float x2 = p[i + HD / 2];
    float c1 = cosf[s * HD + i];
    float s1 = sinf[s * HD + i];
    float c2 = cosf[s * HD + i + HD / 2];
    float s2 = sinf[s * HD + i + HD / 2];
    p[i]          = x1 * c1 - x2 * s1;
    p[i + HD / 2] = x2 * c2 + x1 * s2;
}

// ---------------- FP16 tensor-core flash attention (ldmatrix frags) ------------
#define QW 44                 // words per Q/K row (176 bytes)
#define PW 76                 // words per Vt/Ps row (304 bytes)
#define ATT_WORDS (128 * QW + 128 * QW + 80 * PW + 128 * PW)
#define ATT_SMEM  (ATT_WORDS * 4)       // 108288 bytes

__global__ __launch_bounds__(256) void attn_h16_kernel(
    const float* __restrict__ q, const float* __restrict__ k,
    const float* __restrict__ v, __half* __restrict__ oh)
{
    extern __shared__ unsigned sw[];
    unsigned* Qw = sw;                     // [128][44]
    unsigned* Kw = Qw + 128 * QW;          // [128][44]
    unsigned* Vw = Kw + 128 * QW;          // [80][76]
    unsigned* Pw = Vw + 80 * PW;           // [128][76]
    __half* Vh = (__half*)Vw;
    const uint32_t sbase = (uint32_t)__cvta_generic_to_shared(sw);
    const uint32_t Qb = sbase;
    const uint32_t Kb = Qb + 128 * QW * 4;
    const uint32_t Vb = Kb + 128 * QW * 4;
    const uint32_t Pb = Vb + 80 * PW * 4;

    const int b    = blockIdx.z;
    const int h    = blockIdx.y;
    const int qt   = gridDim.x - 1 - blockIdx.x;   // longest blocks first
    const int kvh  = h >> 2;
    const int tid  = threadIdx.x;
    const int lane = tid & 31;
    const int warp = tid >> 5;
    const int lq   = lane >> 2;
    const int lr   = lane & 3;
    const int wr   = warp * 16;
    const float scale = rsqrtf((float)HD);

    const int arow_l = (lane & 7) + ((lane >> 3) & 1) * 8;
    const int awrd_l = (lane >> 4) * 4;
    const int brow_l = (lane & 7) + (lane >> 4) * 8;
    const int bwrd_l = ((lane >> 3) & 1) * 4;

    // ---- load Q tile (128 x 80) -> half ----
    #pragma unroll
    for (int i = 0; i < 10; i++) {
        int f   = tid + i * 256;
        int row = f / 20;
        int cw  = (f % 20) * 2;
        float4 a = *(const float4*)(q + ((size_t)(b * SEQ + qt * 128 + row)) * (NH * HD)
                                      + h * HD + cw * 2);
        Qw[row * QW + cw    ] = packh2(a.x, a.y);
        Qw[row * QW + cw + 1] = packh2(a.z, a.w);
    }

    float oacc[10][4];
    #pragma unroll
    for (int i = 0; i < 10; i++)
        #pragma unroll
        for (int j = 0; j < 4; j++) oacc[i][j] = 0.f;
    float m0 = -INFINITY, m1 = -INFINITY;
    float l0 = 0.f, l1 = 0.f;

    const int row0 = qt * 128 + wr + lq;
    const int row1 = row0 + 8;

    for (int kt = 0; kt <= qt; kt++) {
        __syncthreads();
        #pragma unroll
        for (int i = 0; i < 10; i++) {
            int f   = tid + i * 256;
            int row = f / 20;
            int cw  = (f % 20) * 2;
            int c4  = cw * 2;
            size_t g = ((size_t)(b * SEQ + kt * 128 + row)) * (NKV * HD) + kvh * HD + c4;
            float4 kk = *(const float4*)(k + g);
            Kw[row * QW + cw    ] = packh2(kk.x, kk.y);
            Kw[row * QW + cw + 1] = packh2(kk.z, kk.w);
            float4 vv = *(const float4*)(v + g);
            Vh[(c4 + 0) * (2 * PW) + row] = __float2half_rn(vv.x);
            Vh[(c4 + 1) * (2 * PW) + row] = __float2half_rn(vv.y);
            Vh[(c4 + 2) * (2 * PW) + row] = __float2half_rn(vv.z);
            Vh[(c4 + 3) * (2 * PW) + row] = __float2half_rn(vv.w);
        }
        __syncthreads();

        // ---- QK^T: S[16 x 128] per warp, 5 k-steps of 16 ----
        float sc[16][4];
        #pragma unroll
        for (int ni = 0; ni < 16; ni++)
            #pragma unroll
            for (int j = 0; j < 4; j++) sc[ni][j] = 0.f;

        #pragma unroll
        for (int ks = 0; ks < 5; ks++) {
            const int c8 = ks * 8;
            unsigned af[4];
            ldsm_x4(af[0], af[1], af[2], af[3],
                    Qb + (uint32_t)(wr + arow_l) * 176 + (uint32_t)(c8 + awrd_l) * 4);
            unsigned bf[16][2];
            #pragma unroll
            for (int nb = 0; nb < 16; nb += 2)
                ldsm_x4(bf[nb][0], bf[nb][1], bf[nb + 1][0], bf[nb + 1][1],
                        Kb + (uint32_t)(nb * 8 + brow_l) * 176
                           + (uint32_t)(c8 + bwrd_l) * 4);
            #pragma unroll
            for (int ni = 0; ni < 16; ni++)
                mma_f16(sc[ni], af, bf[ni][0], bf[ni][1]);
        }

        // ---- scale + causal mask ----
        const bool diag = (kt == qt);
        #pragma unroll
        for (int ni = 0; ni < 16; ni++) {
            int c = kt * 128 + ni * 8 + lr * 2;
            sc[ni][0] = (diag && c     > row0) ? -1e30f : sc[ni][0] * scale;
            sc[ni][1] = (diag && c + 1 > row0) ? -1e30f : sc[ni][1] * scale;
            sc[ni][2] = (diag && c     > row1) ? -1e30f : sc[ni][2] * scale;
            sc[ni][3] = (diag && c + 1 > row1) ? -1e30f : sc[ni][3] * scale;
        }

        // ---- online softmax ----
        float rm0 = -1e30f, rm1 = -1e30f;
        #pragma unroll
        for (int ni = 0; ni < 16; ni++) {
            rm0 = fmaxf(rm0, fmaxf(sc[ni][0], sc[ni][1]));
            rm1 = fmaxf(rm1, fmaxf(sc[ni][2], sc[ni][3]));
        }
        rm0 = fmaxf(rm0, __shfl_xor_sync(0xffffffffu, rm0, 1));
        rm0 = fmaxf(rm0, __shfl_xor_sync(0xffffffffu, rm0, 2));
        rm1 = fmaxf(rm1, __shfl_xor_sync(0xffffffffu, rm1, 1));
        rm1 = fmaxf(rm1, __shfl_xor_sync(0xffffffffu, rm1, 2));

        float m0n = fmaxf(m0, rm0);
        float m1n = fmaxf(m1, rm1);
        float a0  = __expf(m0 - m0n);
        float a1  = __expf(m1 - m1n);
        m0 = m0n; m1 = m1n;

        float rs0 = 0.f, rs1 = 0.f;
        #pragma unroll
        for (int ni = 0; ni < 16; ni++) {
            float p0 = __expf(sc[ni][0] - m0n);
            float p1 = __expf(sc[ni][1] - m0n);
            float p2 = __expf(sc[ni][2] - m1n);
            float p3 = __expf(sc[ni][3] - m1n);
            rs0 += p0 + p1;
            rs1 += p2 + p3;
            Pw[(wr + lq    ) * PW + ni * 4 + lr] = packh2(p0, p1);
            Pw[(wr + lq + 8) * PW + ni * 4 + lr] = packh2(p2, p3);
        }
        rs0 += __shfl_xor_sync(0xffffffffu, rs0, 1);
        rs0 += __shfl_xor_sync(0xffffffffu, rs0, 2);
        rs1 += __shfl_xor_sync(0xffffffffu, rs1, 1);
        rs1 += __shfl_xor_sync(0xffffffffu, rs1, 2);
        l0 = l0 * a0 + rs0;
        l1 = l1 * a1 + rs1;

        #pragma unroll
        for (int ni = 0; ni < 10; ni++) {
            oacc[ni][0] *= a0; oacc[ni][1] *= a0;
            oacc[ni][2] *= a1; oacc[ni][3] *= a1;
        }

        __syncwarp();   // Ps rows are warp-private

        // ---- PV: O[16 x 80] += P[16 x 128] @ V[128 x 80], 8 k-steps ----
        #pragma unroll
        for (int ks = 0; ks < 8; ks++) {
            const int c8 = ks * 8;
            unsigned af[4];
            ldsm_x4(af[0], af[1], af[2], af[3],
                    Pb + (uint32_t)(wr + arow_l) * 304 + (uint32_t)(c8 + awrd_l) * 4);
            unsigned bf[10][2];
            #pragma unroll
            for (int nb = 0; nb < 10; nb += 2)
                ldsm_x4(bf[nb][0], bf[nb][1], bf[nb + 1][0], bf[nb + 1][1],
                        Vb + (uint32_t)(nb * 8 + brow_l) * 304
                           + (uint32_t)(c8 + bwrd_l) * 4);
            #pragma unroll
            for (int ni = 0; ni < 10; ni++)
                mma_f16(oacc[ni], af, bf[ni][0], bf[ni][1]);
        }
    }

    // ---- epilogue: fp16 output feeds the fp16 Wo GEMM ----
    const float inv0 = 1.0f / l0;
    const float inv1 = 1.0f / l1;
    #pragma unroll
    for (int ni = 0; ni < 10; ni++) {
        int c = ni * 8 + lr * 2;
        __half2* p0 = (__half2*)(oh + (size_t)(b * SEQ + row0) * (NH * HD) + h * HD + c);
        __half2* p1 = (__half2*)(oh + (size_t)(b * SEQ + row1) * (NH * HD) + h * HD + c);
        *p0 = __floats2half2_rn(oacc[ni][0] * inv0, oacc[ni][1] * inv0);
        *p1 = __floats2half2_rn(oacc[ni][2] * inv1, oacc[ni][3] * inv1);
    }
}

// ---------------- launch --------------------------------------------------------
extern "C" void kernel_launch(void* const* d_in, const int* in_sizes, int n_in,
                              void* d_out, int out_size)
{
    const float* x    = (const float*)d_in[0];
    const float* cosf = (const float*)d_in[1];
    const float* sinf = (const float*)d_in[2];
    const float* Wq   = (const float*)d_in[3];
    const float* Wk   = (const float*)d_in[4];
    const float* Wv   = (const float*)d_in[5];
    const float* Wo   = (const float*)d_in[6];
    float* out = (float*)d_out;

    float *qb, *kb, *vb;
    __half *ohb, *xh, *wqh, *wkh, *wvh, *woh;
    cudaGetSymbolAddress((void**)&qb, g_q);
    cudaGetSymbolAddress((void**)&kb, g_k);
    cudaGetSymbolAddress((void**)&vb, g_v);
    cudaGetSymbolAddress((void**)&ohb, g_oh);
    cudaGetSymbolAddress((void**)&xh, g_xh);
    cudaGetSymbolAddress((void**)&wqh, g_wqh);
    cudaGetSymbolAddress((void**)&wkh, g_wkh);
    cudaGetSymbolAddress((void**)&wvh, g_wvh);
    cudaGetSymbolAddress((void**)&woh, g_woh);

    // prep: x -> half, weights -> transposed [N,K] half
    {
        int n8 = M_TOK * HIDDEN / 8;
        f2h_kernel<<<(n8 + 255) / 256, 256>>>(x, xh, n8);
        dim3 blk(32, 8);
        f2h_transpose_kernel<<<dim3((NH * HD) / 32, HIDDEN / 32), blk>>>(Wq, wqh, HIDDEN, NH * HD);
        f2h_transpose_kernel<<<dim3((NKV * HD) / 32, HIDDEN / 32), blk>>>(Wk, wkh, HIDDEN, NKV * HD);
        f2h_transpose_kernel<<<dim3((NKV * HD) / 32, HIDDEN / 32), blk>>>(Wv, wvh, HIDDEN, NKV * HD);
        f2h_transpose_kernel<<<dim3(HIDDEN / 32, (NH * HD) / 32), blk>>>(Wo, woh, NH * HD, HIDDEN);
    }

    cudaFuncSetAttribute(h16_gemm3_kernel,
                         cudaFuncAttributeMaxDynamicSharedMemorySize, GEMM_SMEM);

    // fused Q/K/V projections (fp16 mma)
    {
        dim3 g(30, M_TOK / 128);
        h16_gemm3_kernel<<<g, 256, GEMM_SMEM>>>(
            xh,
            wqh, qb, NH * HD, 20,
            wkh, kb, NKV * HD, 25,
            wvh, vb, NKV * HD,
            M_TOK, HIDDEN);
    }

    // fused RoPE
    {
        int tq = M_TOK * NH * (HD / 2);
        int tk = M_TOK * NKV * (HD / 2);
        int tot = tq + tk;
        rope_fused_kernel<<<(tot + 255) / 256, 256>>>(qb, kb, cosf, sinf, tq, tot);
    }

    // attention (fp16 mma flash, ldmatrix)
    {
        cudaFuncSetAttribute(attn_h16_kernel,
                             cudaFuncAttributeMaxDynamicSharedMemorySize, ATT_SMEM);
        dim3 ga(SEQ / 128, NH, BATCH);
        attn_h16_kernel<<<ga, 256, ATT_SMEM>>>(qb, kb, vb, ohb);
    }

    // output projection (fp16 mma)
    {
        dim3 go(HIDDEN / 128, M_TOK / 128);
        h16_gemm3_kernel<<<go, 256, GEMM_SMEM>>>(
            ohb,
            woh, out, HIDDEN, 20,
            woh, out, HIDDEN, 20,
            woh, out, HIDDEN,
            M_TOK, HIDDEN);
    }
}

// round 11
// speedup vs baseline: 1.6418x; 1.0560x over previous
#include <cuda_runtime.h>
#include <cuda_fp16.h>
#include <math.h>
#include <stdint.h>

#define HIDDEN 2560
#define NH 32
#define NKV 8
#define HD 80
#define BATCH 2
#define SEQ 2048
#define M_TOK (BATCH * SEQ)   // 4096

// ---------------- scratch (static device globals; no runtime alloc) ----------
__device__ __half g_qh[M_TOK * NH * HD];
__device__ __half g_kh[M_TOK * NKV * HD];
__device__ __half g_vh[M_TOK * NKV * HD];
__device__ __half g_oh[M_TOK * NH * HD];       // attn out, half, K-major
__device__ __half g_xh[M_TOK * HIDDEN];        // x rounded to half
__device__ __half g_wqh[HIDDEN * NH * HD];     // weights: transposed [N,K] half
__device__ __half g_wkh[HIDDEN * NKV * HD];
__device__ __half g_wvh[HIDDEN * NKV * HD];
__device__ __half g_woh[NH * HD * HIDDEN];

__device__ __forceinline__ void mma_f16(float* c, const unsigned* a,
                                        unsigned b0, unsigned b1) {
    asm volatile(
        "mma.sync.aligned.m16n8k16.row.col.f32.f16.f16.f32 "
        "{%0,%1,%2,%3}, {%4,%5,%6,%7}, {%8,%9}, {%0,%1,%2,%3};"
        : "+f"(c[0]), "+f"(c[1]), "+f"(c[2]), "+f"(c[3])
        : "r"(a[0]), "r"(a[1]), "r"(a[2]), "r"(a[3]),
          "r"(b0), "r"(b1));
}

__device__ __forceinline__ void ldsm_x4(unsigned& r0, unsigned& r1,
                                        unsigned& r2, unsigned& r3,
                                        uint32_t addr) {
    asm volatile("ldmatrix.sync.aligned.m8n8.x4.shared.b16 {%0,%1,%2,%3}, [%4];"
                 : "=r"(r0), "=r"(r1), "=r"(r2), "=r"(r3) : "r"(addr));
}

__device__ __forceinline__ unsigned packh2(float x, float y) {
    __half2 h = __floats2half2_rn(x, y);
    return *(unsigned*)&h;
}

__device__ __forceinline__ void cp_async16(void* smem_ptr, const void* gptr) {
    unsigned saddr = (unsigned)__cvta_generic_to_shared(smem_ptr);
    asm volatile("cp.async.cg.shared.global [%0], [%1], 16;\n"
                 :: "r"(saddr), "l"(gptr));
}
__device__ __forceinline__ void cp_commit() {
    asm volatile("cp.async.commit_group;\n");
}
__device__ __forceinline__ void cp_wait0() {
    asm volatile("cp.async.wait_group 0;\n");
}
__device__ __forceinline__ void cp_wait1() {
    asm volatile("cp.async.wait_group 1;\n");
}

// typed paired store: fp32 -> (float2 | half2)
__device__ __forceinline__ void store2(float* p, float a, float b) {
    *(float2*)p = make_float2(a, b);
}
__device__ __forceinline__ void store2(__half* p, float a, float b) {
    *(__half2*)p = __floats2half2_rn(a, b);
}

// ---------------- prep: fp32 -> fp16, same layout ------------------------------
__global__ void f2h_kernel(const float* __restrict__ in,
                           __half* __restrict__ out, int n8)
{
    int i = blockIdx.x * blockDim.x + threadIdx.x;
    if (i >= n8) return;
    const float4* ip = (const float4*)in + (size_t)i * 2;
    float4 a = ip[0], b = ip[1];
    uint4 o;
    o.x = packh2(a.x, a.y); o.y = packh2(a.z, a.w);
    o.z = packh2(b.x, b.y); o.w = packh2(b.z, b.w);
    *((uint4*)out + i) = o;
}

// ---------------- prep: transpose [K,N] fp32 -> [N,K] fp16 ---------------------
__global__ void f2h_transpose_kernel(const float* __restrict__ in,
                                     __half* __restrict__ out,
                                     int Kdim, int Ndim)
{
    __shared__ float t[32][33];
    int n0 = blockIdx.x * 32, k0 = blockIdx.y * 32;
    #pragma unroll
    for (int j = 0; j < 4; j++)
        t[threadIdx.y + j * 8][threadIdx.x] =
            in[(size_t)(k0 + threadIdx.y + j * 8) * Ndim + n0 + threadIdx.x];
    __syncthreads();
    #pragma unroll
    for (int j = 0; j < 4; j++)
        out[(size_t)(n0 + threadIdx.y + j * 8) * Kdim + k0 + threadIdx.x] =
            __float2half_rn(t[threadIdx.x][threadIdx.y + j * 8]);
}

// ---------------- pipelined FP16 GEMM (3-stage, ldmatrix), 3 segments ----------
#define HSTR 40                         // halves per smem row (80 bytes)
#define TILEH (128 * HSTR)              // halves per tile = 5120
#define STGH  (2 * TILEH)               // halves per stage (A+B)
#define GEMM_SMEM (3 * STGH * 2)        // 61440 bytes

template <typename OutT>
__global__ __launch_bounds__(256) void h16_gemm3_kernel(
    const __half* __restrict__ A,
    const __half* __restrict__ B0, OutT* __restrict__ C0, int N0, int xs0,
    const __half* __restrict__ B1, OutT* __restrict__ C1, int N1, int xs1,
    const __half* __restrict__ B2, OutT* __restrict__ C2, int N2,
    int M, int K)
{
    extern __shared__ __half smh[];
    const uint32_t sbase = (uint32_t)__cvta_generic_to_shared(smh);

    const int bx = blockIdx.x;
    const __half* B; OutT* C; int N; int bxl;
    if (bx < xs0)      { B = B0; C = C0; N = N0; bxl = bx; }
    else if (bx < xs1) { B = B1; C = C1; N = N1; bxl = bx - xs0; }
    else               { B = B2; C = C2; N = N2; bxl = bx - xs1; }

    const int tid  = threadIdx.x;
    const int lane = tid & 31;
    const int warp = tid >> 5;
    const int wm   = (warp & 3) * 32;
    const int wn   = (warp >> 2) * 64;
    const int bm   = blockIdx.y * 128;
    const int bn   = bxl * 128;
    const int lq   = lane >> 2;
    const int lr   = lane & 3;

    const int arow_l = (lane & 7) + ((lane >> 3) & 1) * 8;
    const int awrd_l = (lane >> 4) * 4;
    const int brow_l = (lane & 7) + (lane >> 4) * 8;
    const int bwrd_l = ((lane >> 3) & 1) * 4;

    const int cr = tid >> 2;
    const int cc = tid & 3;

    float acc[2][8][4];
    #pragma unroll
    for (int i = 0; i < 2; i++)
        #pragma unroll
        for (int j = 0; j < 8; j++)
            #pragma unroll
            for (int r = 0; r < 4; r++) acc[i][j][r] = 0.f;

    const int T = K / 32;

    auto issue = [&](int t) {
        __half* sA = smh + (t % 3) * STGH;
        __half* sB = sA + TILEH;
        const int k0 = t * 32;
        #pragma unroll
        for (int i = 0; i < 2; i++) {
            int r = cr + i * 64;
            cp_async16(sA + r * HSTR + cc * 8, A + (size_t)(bm + r) * K + k0 + cc * 8);
            cp_async16(sB + r * HSTR + cc * 8, B + (size_t)(bn + r) * K + k0 + cc * 8);
        }
    };

    issue(0); cp_commit();
    issue(1); cp_commit();

    for (int t = 0; t < T; t++) {
        cp_wait1();
        __syncthreads();            // stage t ready; stage t-1 free for all warps

        if (t + 2 < T) issue(t + 2);
        cp_commit();                // keep group count consistent (may be empty)

        const uint32_t stA = sbase + (uint32_t)((t % 3) * STGH) * 2;
        const uint32_t stB = stA + TILEH * 2;
        #pragma unroll
        for (int ks = 0; ks < 2; ks++) {
            const int c8 = ks * 8;
            unsigned af[2][4];
            #pragma unroll
            for (int mi = 0; mi < 2; mi++)
                ldsm_x4(af[mi][0], af[mi][1], af[mi][2], af[mi][3],
                        stA + (uint32_t)(wm + mi * 16 + arow_l) * 80
                            + (uint32_t)(c8 + awrd_l) * 4);
            unsigned bf[8][2];
            #pragma unroll
            for (int nb = 0; nb < 8; nb += 2)
                ldsm_x4(bf[nb][0], bf[nb][1], bf[nb + 1][0], bf[nb + 1][1],
                        stB + (uint32_t)(wn + nb * 8 + brow_l) * 80
                            + (uint32_t)(c8 + bwrd_l) * 4);
            #pragma unroll
            for (int mi = 0; mi < 2; mi++)
                #pragma unroll
                for (int ni = 0; ni < 8; ni++)
                    mma_f16(acc[mi][ni], af[mi], bf[ni][0], bf[ni][1]);
        }
    }

    #pragma unroll
    for (int mi = 0; mi < 2; mi++) {
        int m = bm + wm + mi * 16 + lq;
        #pragma unroll
        for (int ni = 0; ni < 8; ni++) {
            int n = bn + wn + ni * 8 + lr * 2;
            store2(C + (size_t)m * N + n,       acc[mi][ni][0], acc[mi][ni][1]);
            store2(C + (size_t)(m + 8) * N + n, acc[mi][ni][2], acc[mi][ni][3]);
        }
    }
}

// ---------------- fused RoPE over q and k (half in/out) ------------------------
__global__ void rope_fused_kernel(__half* __restrict__ qb, __half* __restrict__ kb,
                                  const float* __restrict__ cosf,
                                  const float* __restrict__ sinf,
                                  int tq, int total)
{
    int idx = blockIdx.x * blockDim.x + threadIdx.x;
    if (idx >= total) return;
    __half* t; int nheads; int li;
    if (idx < tq) { t = qb; nheads = NH;  li = idx; }
    else          { t = kb; nheads = NKV; li = idx - tq; }

    int i   = li % (HD / 2);
    int h   = (li / (HD / 2)) % nheads;
    int tok = li / ((HD / 2) * nheads);
    int s   = tok % SEQ;

    __half* p = t + (size_t)tok * nheads * HD + h * HD;
    float x1 = __half2float(p[i]);
    float x2 = __half2float(p[i + HD / 2]);
    float c1 = cosf[s * HD + i];
    float s1 = sinf[s * HD + i];
    float c2 = cosf[s * HD + i + HD / 2];
    float s2 = sinf[s * HD + i + HD / 2];
    p[i]          = __float2half_rn(x1 * c1 - x2 * s1);
    p[i + HD / 2] = __float2half_rn(x2 * c2 + x1 * s2);
}

// ---------------- FP16 flash attention (half inputs, cp.async Q/K) -------------
#define QW 44                 // words per Q/K row (176 bytes)
#define PW 76                 // words per Vt/Ps row (304 bytes)
#define ATT_WORDS (128 * QW + 128 * QW + 80 * PW + 128 * PW)
#define ATT_SMEM  (ATT_WORDS * 4)       // 108288 bytes

__global__ __launch_bounds__(256) void attn_h16_kernel(
    const __half* __restrict__ q, const __half* __restrict__ k,
    const __half* __restrict__ v, __half* __restrict__ oh)
{
    extern __shared__ unsigned sw[];
    unsigned* Qw = sw;                     // [128][44]
    unsigned* Kw = Qw + 128 * QW;          // [128][44]
    unsigned* Vw = Kw + 128 * QW;          // [80][76]
    unsigned* Pw = Vw + 80 * PW;           // [128][76]
    __half* Qh = (__half*)Qw;
    __half* Kh = (__half*)Kw;
    __half* Vh = (__half*)Vw;
    const uint32_t sbase = (uint32_t)__cvta_generic_to_shared(sw);
    const uint32_t Qb = sbase;
    const uint32_t Kb = Qb + 128 * QW * 4;
    const uint32_t Vb = Kb + 128 * QW * 4;
    const uint32_t Pb = Vb + 80 * PW * 4;

    const int b    = blockIdx.z;
    const int h    = blockIdx.y;
    const int qt   = gridDim.x - 1 - blockIdx.x;   // longest blocks first
    const int kvh  = h >> 2;
    const int tid  = threadIdx.x;
    const int lane = tid & 31;
    const int warp = tid >> 5;
    const int lq   = lane >> 2;
    const int lr   = lane & 3;
    const int wr   = warp * 16;
    const float scale = rsqrtf((float)HD);

    const int arow_l = (lane & 7) + ((lane >> 3) & 1) * 8;
    const int awrd_l = (lane >> 4) * 4;
    const int brow_l = (lane & 7) + (lane >> 4) * 8;
    const int bwrd_l = ((lane >> 3) & 1) * 4;

    // ---- load Q tile (128 x 80 half) via cp.async ----
    {
        const __half* qsrc = q + ((size_t)(b * SEQ + qt * 128)) * (NH * HD) + h * HD;
        #pragma unroll
        for (int i = 0; i < 5; i++) {
            int f   = tid + i * 256;
            int row = f / 10;
            int ch  = f % 10;
            cp_async16(Qh + row * 88 + ch * 8,
                       qsrc + (size_t)row * (NH * HD) + ch * 8);
        }
        cp_commit();
    }

    float oacc[10][4];
    #pragma unroll
    for (int i = 0; i < 10; i++)
        #pragma unroll
        for (int j = 0; j < 4; j++) oacc[i][j] = 0.f;
    float m0 = -INFINITY, m1 = -INFINITY;
    float l0 = 0.f, l1 = 0.f;

    const int row0 = qt * 128 + wr + lq;
    const int row1 = row0 + 8;

    for (int kt = 0; kt <= qt; kt++) {
        __syncthreads();   // previous iteration fully consumed K/V/P smem
        // ---- K via cp.async; V^T manual scatter (80 x 128 half) ----
        {
            const __half* ksrc = k + ((size_t)(b * SEQ + kt * 128)) * (NKV * HD) + kvh * HD;
            const __half* vsrc = v + ((size_t)(b * SEQ + kt * 128)) * (NKV * HD) + kvh * HD;
            #pragma unroll
            for (int i = 0; i < 5; i++) {
                int f   = tid + i * 256;
                int row = f / 10;
                int ch  = f % 10;
                cp_async16(Kh + row * 88 + ch * 8,
                           ksrc + (size_t)row * (NKV * HD) + ch * 8);
                uint4 vv = *(const uint4*)(vsrc + (size_t)row * (NKV * HD) + ch * 8);
                __half hv[8];
                *(uint4*)hv = vv;
                #pragma unroll
                for (int j = 0; j < 8; j++)
                    Vh[(ch * 8 + j) * (2 * PW) + row] = hv[j];
            }
            cp_commit();
            cp_wait0();
        }
        __syncthreads();

        // ---- QK^T: S[16 x 128] per warp, 5 k-steps of 16 ----
        float sc[16][4];
        #pragma unroll
        for (int ni = 0; ni < 16; ni++)
            #pragma unroll
            for (int j = 0; j < 4; j++) sc[ni][j] = 0.f;

        #pragma unroll
        for (int ks = 0; ks < 5; ks++) {
            const int c8 = ks * 8;
            unsigned af[4];
            ldsm_x4(af[0], af[1], af[2], af[3],
                    Qb + (uint32_t)(wr + arow_l) * 176 + (uint32_t)(c8 + awrd_l) * 4);
            unsigned bf[16][2];
            #pragma unroll
            for (int nb = 0; nb < 16; nb += 2)
                ldsm_x4(bf[nb][0], bf[nb][1], bf[nb + 1][0], bf[nb + 1][1],
                        Kb + (uint32_t)(nb * 8 + brow_l) * 176
                           + (uint32_t)(c8 + bwrd_l) * 4);
            #pragma unroll
            for (int ni = 0; ni < 16; ni++)
                mma_f16(sc[ni], af, bf[ni][0], bf[ni][1]);
        }

        // ---- scale + causal mask ----
        const bool diag = (kt == qt);
        #pragma unroll
        for (int ni = 0; ni < 16; ni++) {
            int c = kt * 128 + ni * 8 + lr * 2;
            sc[ni][0] = (diag && c     > row0) ? -1e30f : sc[ni][0] * scale;
            sc[ni][1] = (diag && c + 1 > row0) ? -1e30f : sc[ni][1] * scale;
            sc[ni][2] = (diag && c     > row1) ? -1e30f : sc[ni][2] * scale;
            sc[ni][3] = (diag && c + 1 > row1) ? -1e30f : sc[ni][3] * scale;
        }

        // ---- online softmax ----
        float rm0 = -1e30f, rm1 = -1e30f;
        #pragma unroll
        for (int ni = 0; ni < 16; ni++) {
            rm0 = fmaxf(rm0, fmaxf(sc[ni][0], sc[ni][1]));
            rm1 = fmaxf(rm1, fmaxf(sc[ni][2], sc[ni][3]));
        }
        rm0 = fmaxf(rm0, __shfl_xor_sync(0xffffffffu, rm0, 1));
        rm0 = fmaxf(rm0, __shfl_xor_sync(0xffffffffu, rm0, 2));
        rm1 = fmaxf(rm1, __shfl_xor_sync(0xffffffffu, rm1, 1));
        rm1 = fmaxf(rm1, __shfl_xor_sync(0xffffffffu, rm1, 2));

        float m0n = fmaxf(m0, rm0);
        float m1n = fmaxf(m1, rm1);
        float a0  = __expf(m0 - m0n);
        float a1  = __expf(m1 - m1n);
        m0 = m0n; m1 = m1n;

        float rs0 = 0.f, rs1 = 0.f;
        #pragma unroll
        for (int ni = 0; ni < 16; ni++) {
            float p0 = __expf(sc[ni][0] - m0n);
            float p1 = __expf(sc[ni][1] - m0n);
            float p2 = __expf(sc[ni][2] - m1n);
            float p3 = __expf(sc[ni][3] - m1n);
            rs0 += p0 + p1;
            rs1 += p2 + p3;
            Pw[(wr + lq    ) * PW + ni * 4 + lr] = packh2(p0, p1);
            Pw[(wr + lq + 8) * PW + ni * 4 + lr] = packh2(p2, p3);
        }
        rs0 += __shfl_xor_sync(0xffffffffu, rs0, 1);
        rs0 += __shfl_xor_sync(0xffffffffu, rs0, 2);
        rs1 += __shfl_xor_sync(0xffffffffu, rs1, 1);
        rs1 += __shfl_xor_sync(0xffffffffu, rs1, 2);
        l0 = l0 * a0 + rs0;
        l1 = l1 * a1 + rs1;

        #pragma unroll
        for (int ni = 0; ni < 10; ni++) {
            oacc[ni][0] *= a0; oacc[ni][1] *= a0;
            oacc[ni][2] *= a1; oacc[ni][3] *= a1;
        }

        __syncwarp();   // Ps rows are warp-private

        // ---- PV: O[16 x 80] += P[16 x 128] @ V[128 x 80], 8 k-steps ----
        #pragma unroll
        for (int ks = 0; ks < 8; ks++) {
            const int c8 = ks * 8;
            unsigned af[4];
            ldsm_x4(af[0], af[1], af[2], af[3],
                    Pb + (uint32_t)(wr + arow_l) * 304 + (uint32_t)(c8 + awrd_l) * 4);
            unsigned bf[10][2];
            #pragma unroll
            for (int nb = 0; nb < 10; nb += 2)
                ldsm_x4(bf[nb][0], bf[nb][1], bf[nb + 1][0], bf[nb + 1][1],
                        Vb + (uint32_t)(nb * 8 + brow_l) * 304
                           + (uint32_t)(c8 + bwrd_l) * 4);
            #pragma unroll
            for (int ni = 0; ni < 10; ni++)
                mma_f16(oacc[ni], af, bf[ni][0], bf[ni][1]);
        }
    }

    // ---- epilogue: fp16 output feeds the fp16 Wo GEMM ----
    const float inv0 = 1.0f / l0;
    const float inv1 = 1.0f / l1;
    #pragma unroll
    for (int ni = 0; ni < 10; ni++) {
        int c = ni * 8 + lr * 2;
        __half2* p0 = (__half2*)(oh + (size_t)(b * SEQ + row0) * (NH * HD) + h * HD + c);
        __half2* p1 = (__half2*)(oh + (size_t)(b * SEQ + row1) * (NH * HD) + h * HD + c);
        *p0 = __floats2half2_rn(oacc[ni][0] * inv0, oacc[ni][1] * inv0);
        *p1 = __floats2half2_rn(oacc[ni][2] * inv1, oacc[ni][3] * inv1);
    }
}

// ---------------- launch --------------------------------------------------------
extern "C" void kernel_launch(void* const* d_in, const int* in_sizes, int n_in,
                              void* d_out, int out_size)
{
    const float* x    = (const float*)d_in[0];
    const float* cosf = (const float*)d_in[1];
    const float* sinf = (const float*)d_in[2];
    const float* Wq   = (const float*)d_in[3];
    const float* Wk   = (const float*)d_in[4];
    const float* Wv   = (const float*)d_in[5];
    const float* Wo   = (const float*)d_in[6];
    float* out = (float*)d_out;

    __half *qhb, *khb, *vhb, *ohb, *xh, *wqh, *wkh, *wvh, *woh;
    cudaGetSymbolAddress((void**)&qhb, g_qh);
    cudaGetSymbolAddress((void**)&khb, g_kh);
    cudaGetSymbolAddress((void**)&vhb, g_vh);
    cudaGetSymbolAddress((void**)&ohb, g_oh);
    cudaGetSymbolAddress((void**)&xh, g_xh);
    cudaGetSymbolAddress((void**)&wqh, g_wqh);
    cudaGetSymbolAddress((void**)&wkh, g_wkh);
    cudaGetSymbolAddress((void**)&wvh, g_wvh);
    cudaGetSymbolAddress((void**)&woh, g_woh);

    // prep: x -> half, weights -> transposed [N,K] half
    {
        int n8 = M_TOK * HIDDEN / 8;
        f2h_kernel<<<(n8 + 255) / 256, 256>>>(x, xh, n8);
        dim3 blk(32, 8);
        f2h_transpose_kernel<<<dim3((NH * HD) / 32, HIDDEN / 32), blk>>>(Wq, wqh, HIDDEN, NH * HD);
        f2h_transpose_kernel<<<dim3((NKV * HD) / 32, HIDDEN / 32), blk>>>(Wk, wkh, HIDDEN, NKV * HD);
        f2h_transpose_kernel<<<dim3((NKV * HD) / 32, HIDDEN / 32), blk>>>(Wv, wvh, HIDDEN, NKV * HD);
        f2h_transpose_kernel<<<dim3(HIDDEN / 32, (NH * HD) / 32), blk>>>(Wo, woh, NH * HD, HIDDEN);
    }

    cudaFuncSetAttribute(h16_gemm3_kernel<__half>,
                         cudaFuncAttributeMaxDynamicSharedMemorySize, GEMM_SMEM);
    cudaFuncSetAttribute(h16_gemm3_kernel<float>,
                         cudaFuncAttributeMaxDynamicSharedMemorySize, GEMM_SMEM);

    // fused Q/K/V projections (fp16 mma, half outputs)
    {
        dim3 g(30, M_TOK / 128);
        h16_gemm3_kernel<__half><<<g, 256, GEMM_SMEM>>>(
            xh,
            wqh, qhb, NH * HD, 20,
            wkh, khb, NKV * HD, 25,
            wvh, vhb, NKV * HD,
            M_TOK, HIDDEN);
    }

    // fused RoPE (half in/out)
    {
        int tq = M_TOK * NH * (HD / 2);
        int tk = M_TOK * NKV * (HD / 2);
        int tot = tq + tk;
        rope_fused_kernel<<<(tot + 255) / 256, 256>>>(qhb, khb, cosf, sinf, tq, tot);
    }

    // attention (fp16 mma flash, half inputs)
    {
        cudaFuncSetAttribute(attn_h16_kernel,
                             cudaFuncAttributeMaxDynamicSharedMemorySize, ATT_SMEM);
        dim3 ga(SEQ / 128, NH, BATCH);
        attn_h16_kernel<<<ga, 256, ATT_SMEM>>>(qhb, khb, vhb, ohb);
    }

    // output projection (fp16 mma, fp32 output)
    {
        dim3 go(HIDDEN / 128, M_TOK / 128);
        h16_gemm3_kernel<float><<<go, 256, GEMM_SMEM>>>(
            ohb,
            woh, out, HIDDEN, 20,
            woh, out, HIDDEN, 20,
            woh, out, HIDDEN,
            M_TOK, HIDDEN);
    }
}